// round 6
// baseline (speedup 1.0000x reference)
#include <cuda_runtime.h>
#include <math.h>
#include <stdint.h>

#define Bx   8
#define Sx   2048
#define Hx   8
#define Mh   64
#define HMx  512

// ---------------------------------------------------------------------------
// Global scratch (allocation-free rule)
// ---------------------------------------------------------------------------
__device__ float g_xp[(size_t)Bx * Sx * HMx];   // x  in A-frag pack (tf32)
__device__ float g_q [(size_t)Bx * Sx * HMx];   // Q  in A-frag pack (pre-scaled)
__device__ float g_k [(size_t)Bx * Sx * HMx];   // K  in paired B-frag pack
__device__ float g_v [(size_t)Bx * Sx * HMx];   // V  in paired B-frag pack
__device__ float g_m [(size_t)Bx * Sx * HMx];   // msgs in A-frag pack (tf32)
__device__ float g_wq[512 * 512];
__device__ float g_wk[512 * 512];
__device__ float g_wv[512 * 512];
__device__ float g_wo[512 * 512];
__device__ unsigned long long g_mb[(size_t)Bx * Sx * 32];  // mask bitwords

__device__ __forceinline__ uint32_t f2tf(float x) {
    uint32_t r;
    asm("cvt.rna.tf32.f32 %0, %1;" : "=r"(r) : "f"(x));
    return r;
}
__device__ __forceinline__ void mma_tf32(float* c, const uint32_t* a,
                                         uint32_t b0, uint32_t b1) {
    asm volatile(
        "mma.sync.aligned.m16n8k8.row.col.f32.tf32.tf32.f32 "
        "{%0,%1,%2,%3}, {%4,%5,%6,%7}, {%8,%9}, {%0,%1,%2,%3};"
        : "+f"(c[0]), "+f"(c[1]), "+f"(c[2]), "+f"(c[3])
        : "r"(a[0]), "r"(a[1]), "r"(a[2]), "r"(a[3]), "r"(b0), "r"(b1));
}

// Layouts (tf32 bit patterns stored as float):
// A-pack:  off = mb*8192 + dg*128 + lane*4 + idx
// W-pack (paired jg): off = dg*4096 + jp*128 + lane*4 + jo*2 + s
// K-pack (paired jt): off(bh) = d*16384 + jtp*128 + lane*4 + jto*2 + s
// V-pack (paired j):  off(bh) = kc*512 + jp*128 + lane*4 + jo*2 + s

// ---------------------------------------------------------------------------
// prep: x[16384,512] -> A-pack tf32
// ---------------------------------------------------------------------------
__global__ void prep_x_kernel(const float* __restrict__ x, float* __restrict__ xp)
{
    int t  = blockIdx.x * 256 + threadIdx.x;
    int r  = t >> 7;
    int c4 = (t & 127) << 2;
    float4 v = *(const float4*)&x[(size_t)r * 512 + c4];
    int mb = r >> 4, rr = r & 15;
    int qrp = rr & 7, hi = rr >> 3;
    float vv[4] = {v.x, v.y, v.z, v.w};
#pragma unroll
    for (int i = 0; i < 4; i++) {
        int col = c4 + i;
        int dg = col >> 3, cc = col & 7;
        int lane = qrp * 4 + (cc & 3);
        int idx  = hi + ((cc >> 2) << 1);
        xp[(size_t)(mb * 64 + dg) * 128 + lane * 4 + idx] =
            __uint_as_float(f2tf(vv[i]));
    }
}

// ---------------------------------------------------------------------------
// prep: W[512,512] -> paired W-pack tf32 (optional exact pow2 prescale)
// ---------------------------------------------------------------------------
__global__ void prep_w_kernel(const float* __restrict__ Wsrc,
                              float* __restrict__ wp, float scale)
{
    int t  = blockIdx.x * 256 + threadIdx.x;
    int k  = t >> 7;
    int c4 = (t & 127) << 2;
    float4 v = *(const float4*)&Wsrc[(size_t)k * 512 + c4];
    int dg = k >> 3, kk = k & 7;
    int s  = kk >> 2;
    float vv[4] = {v.x, v.y, v.z, v.w};
#pragma unroll
    for (int i = 0; i < 4; i++) {
        int n = c4 + i;
        int jg = n >> 3, nn = n & 7;
        int lane = nn * 4 + (kk & 3);
        wp[(size_t)dg * 4096 + (jg >> 1) * 128 + lane * 4 + (jg & 1) * 2 + s] =
            __uint_as_float(f2tf(vv[i] * scale));
    }
}

// ---------------------------------------------------------------------------
// prep: mask[B,S,S] float -> 64-bit words
// ---------------------------------------------------------------------------
__global__ void prep_mask_kernel(const float* __restrict__ mask,
                                 unsigned long long* __restrict__ mb)
{
    int warp = blockIdx.x * 8 + (threadIdx.x >> 5);
    int lane = threadIdx.x & 31;
    const float* row = mask + (size_t)warp * 2048;
    unsigned long long* dst = mb + (size_t)warp * 32;
#pragma unroll 4
    for (int w = 0; w < 32; w++) {
        float m0 = row[w * 64 + lane];
        float m1 = row[w * 64 + 32 + lane];
        unsigned b0 = __ballot_sync(0xffffffffu, m0 > 0.5f);
        unsigned b1 = __ballot_sync(0xffffffffu, m1 > 0.5f);
        if (lane == 0)
            dst[w] = ((unsigned long long)b1 << 32) | b0;
    }
}

// ---------------------------------------------------------------------------
// tf32 GEMM, smem-free, M=32 per warp (2 row-tiles share W frags).
// grid (8, 128), 128 thr. MODE: 0=fp32 out, 1=K-pack, 2=V-pack, 3=A-pack
// ---------------------------------------------------------------------------
template<int MODE>
__global__ void __launch_bounds__(128) gemm_tc_kernel(
    const float* __restrict__ Ap, const float* __restrict__ Wp,
    const float* __restrict__ bias, float* __restrict__ out, float bscale)
{
    const int w    = threadIdx.x >> 5;
    const int lane = threadIdx.x & 31;
    const int qr   = lane >> 2;
    const int qc   = lane & 3;
    const int nb   = blockIdx.x;              // 64-col block == head for K/V
    const int mb0  = blockIdx.y * 8 + w * 2;  // first 16-row group of warp

    float o[2][8][4];
#pragma unroll
    for (int rt = 0; rt < 2; rt++)
#pragma unroll
        for (int j = 0; j < 8; j++)
#pragma unroll
            for (int u = 0; u < 4; u++) o[rt][j][u] = 0.f;

    const float* ab    = Ap + (size_t)mb0 * 8192 + lane * 4;
    const float* wbase = Wp + (size_t)nb * 512 + lane * 4;

    for (int ck = 0; ck < 8; ck++) {
        uint32_t qa[2][8][4];
#pragma unroll
        for (int rt = 0; rt < 2; rt++)
#pragma unroll
            for (int dd = 0; dd < 8; dd++) {
                float4 a4 = *(const float4*)(ab + rt * 8192 + (ck * 8 + dd) * 128);
                qa[rt][dd][0] = __float_as_uint(a4.x);
                qa[rt][dd][1] = __float_as_uint(a4.y);
                qa[rt][dd][2] = __float_as_uint(a4.z);
                qa[rt][dd][3] = __float_as_uint(a4.w);
            }
#pragma unroll
        for (int dd = 0; dd < 8; dd++) {
            const float* wd = wbase + (size_t)(ck * 8 + dd) * 4096;
#pragma unroll
            for (int jp = 0; jp < 4; jp++) {
                float4 wv = *(const float4*)(wd + jp * 128);
                uint32_t b0 = __float_as_uint(wv.x), b1 = __float_as_uint(wv.y);
                uint32_t b2 = __float_as_uint(wv.z), b3 = __float_as_uint(wv.w);
                mma_tf32(o[0][jp * 2],     qa[0][dd], b0, b1);
                mma_tf32(o[0][jp * 2 + 1], qa[0][dd], b2, b3);
                mma_tf32(o[1][jp * 2],     qa[1][dd], b0, b1);
                mma_tf32(o[1][jp * 2 + 1], qa[1][dd], b2, b3);
            }
        }
    }

    const int n0 = nb * 64;

#pragma unroll
    for (int rt = 0; rt < 2; rt++) {
        const int mb  = mb0 + rt;
        const int rlo = mb * 16 + qr;

        if (MODE == 0) {
            const int rhi = rlo + 8;
#pragma unroll
            for (int jc = 0; jc < 8; jc++) {
                int col = n0 + jc * 8 + 2 * qc;
                float2 bb = *(const float2*)&bias[col];
                float2 lo_v = {o[rt][jc][0] + bb.x, o[rt][jc][1] + bb.y};
                float2 hi_v = {o[rt][jc][2] + bb.x, o[rt][jc][3] + bb.y};
                *(float2*)&out[(size_t)rlo * 512 + col] = lo_v;
                *(float2*)&out[(size_t)rhi * 512 + col] = hi_v;
            }
        } else if (MODE == 3) {
#pragma unroll
            for (int jc = 0; jc < 8; jc++) {
                int dg = nb * 8 + jc;
                float2 bb = *(const float2*)&bias[n0 + jc * 8 + 2 * qc];
                bb.x *= bscale; bb.y *= bscale;
                float* base = out + (size_t)(mb * 64 + dg) * 128;
#pragma unroll
                for (int e = 0; e < 2; e++) {
                    int cc = 2 * qc + e;
                    int la = qr * 4 + (cc & 3);
                    int ix = (cc >> 2) << 1;
                    float bv = e ? bb.y : bb.x;
                    base[la * 4 + ix]     = __uint_as_float(f2tf(o[rt][jc][e]     + bv));
                    base[la * 4 + ix + 1] = __uint_as_float(f2tf(o[rt][jc][e + 2] + bv));
                }
            }
        } else if (MODE == 1) {
            int b   = rlo >> 11;
            int tok = rlo & 2047;
            int jtp = tok >> 4;
            int qrk = tok & 7;
            float* base = out + (size_t)(b * 8 + nb) * 131072;
#pragma unroll
            for (int jc = 0; jc < 8; jc++) {
                float2 bb = *(const float2*)&bias[n0 + jc * 8 + 2 * qc];
                float* dbase = base + (size_t)jc * 16384 + jtp * 128;
#pragma unroll
                for (int e = 0; e < 2; e++) {
                    int cc = 2 * qc + e;
                    int lk = qrk * 4 + (cc & 3);
                    int s  = cc >> 2;
                    float bv = e ? bb.y : bb.x;
                    dbase[lk * 4 + s]     = __uint_as_float(f2tf(o[rt][jc][e]     + bv));
                    dbase[lk * 4 + 2 + s] = __uint_as_float(f2tf(o[rt][jc][e + 2] + bv));
                }
            }
        } else {
            int b   = rlo >> 11;
            int tok = rlo & 2047;
            int kc_lo = tok >> 3;
            int s_v   = (tok & 7) >> 2;
            int t4    = tok & 3;
            float* base = out + (size_t)(b * 8 + nb) * 131072;
#pragma unroll
            for (int jc = 0; jc < 8; jc++) {
                float2 bb = *(const float2*)&bias[n0 + jc * 8 + 2 * qc];
                size_t off = (size_t)(jc >> 1) * 128 + (jc & 1) * 2 + s_v;
#pragma unroll
                for (int e = 0; e < 2; e++) {
                    int cc = 2 * qc + e;
                    int lv = cc * 4 + t4;
                    float bv = e ? bb.y : bb.x;
                    base[(size_t)kc_lo * 512 + off + lv * 4] =
                        __uint_as_float(f2tf(o[rt][jc][e] + bv));
                    base[(size_t)(kc_lo + 1) * 512 + off + lv * 4] =
                        __uint_as_float(f2tf(o[rt][jc][e + 2] + bv));
                }
            }
        }
    }
}

// ---------------------------------------------------------------------------
// tf32 flash attention, smem-free. Q reloaded per chunk (L1-resident) to cut
// register pressure; 4 blocks/SM forced for occupancy.
// ---------------------------------------------------------------------------
__global__ void __launch_bounds__(128, 4) attn_tc_kernel(
    const float* __restrict__ Qp, const float* __restrict__ Kp,
    const float* __restrict__ Vp, const unsigned long long* __restrict__ mb,
    float* __restrict__ Mp)
{
    const int h  = blockIdx.z;
    const int b  = blockIdx.y;
    const int q0 = blockIdx.x * 64;
    const int tid  = threadIdx.x;
    const int w    = tid >> 5;
    const int lane = tid & 31;
    const int qr   = lane >> 2;
    const int qc   = lane & 3;

    const int mbq = b * 128 + (q0 >> 4) + w;
    const float* qb = Qp + (size_t)mbq * 8192 + h * 1024 + lane * 4;

    float o[8][4];
#pragma unroll
    for (int j = 0; j < 8; j++)
#pragma unroll
        for (int u = 0; u < 4; u++) o[j][u] = 0.f;
    float m_lo = -INFINITY, m_hi = -INFINITY;
    float l_lo = 0.f, l_hi = 0.f;

    const int rlo = w * 16 + qr;
    const int rhi = rlo + 8;
    const unsigned long long* mb_lo = mb + (size_t)(b * Sx + q0 + rlo) * 32;
    const unsigned long long* mb_hi = mb + (size_t)(b * Sx + q0 + rhi) * 32;

    const size_t bh = (size_t)(b * 8 + h);
    const float* kbase = Kp + bh * 131072 + lane * 4;
    const float* vbase = Vp + bh * 131072 + lane * 4;

    const int srcA = (qr << 2) + (qc >> 1);
    const int srcB = srcA + 2;
    const bool esel = (qc & 1);
    const int bidx0 = 2 * qc;

    for (int t0 = 0; t0 < Sx; t0 += 64) {
        const int jtp0 = t0 >> 4;
        const int jt0  = t0 >> 3;

        // ---- Q fragments (reload per chunk; L1-resident, pre-scaled) ----
        uint32_t qa[8][4];
#pragma unroll
        for (int dd = 0; dd < 8; dd++) {
            float4 a4 = *(const float4*)(qb + dd * 128);
            qa[dd][0] = __float_as_uint(a4.x);
            qa[dd][1] = __float_as_uint(a4.y);
            qa[dd][2] = __float_as_uint(a4.z);
            qa[dd][3] = __float_as_uint(a4.w);
        }

        // ---- S = Q K^T ----
        float s[8][4];
#pragma unroll
        for (int j = 0; j < 8; j++)
#pragma unroll
            for (int u = 0; u < 4; u++) s[j][u] = 0.f;
#pragma unroll
        for (int dd = 0; dd < 8; dd++) {
            const float* kd = kbase + dd * 16384 + jtp0 * 128;
#pragma unroll
            for (int jp = 0; jp < 4; jp++) {
                float4 kv = *(const float4*)(kd + jp * 128);
                mma_tf32(s[jp * 2],     qa[dd],
                         __float_as_uint(kv.x), __float_as_uint(kv.y));
                mma_tf32(s[jp * 2 + 1], qa[dd],
                         __float_as_uint(kv.z), __float_as_uint(kv.w));
            }
        }

        // ---- mask (bitwords) + row max ----
        unsigned long long wlo = mb_lo[t0 >> 6];
        unsigned long long whi = mb_hi[t0 >> 6];
        float rmax_lo = -INFINITY, rmax_hi = -INFINITY;
#pragma unroll
        for (int j = 0; j < 8; j++) {
            int idx = j * 8 + bidx0;
            s[j][0] = ((wlo >> idx) & 1ull)       ? s[j][0] : -INFINITY;
            s[j][1] = ((wlo >> (idx + 1)) & 1ull) ? s[j][1] : -INFINITY;
            s[j][2] = ((whi >> idx) & 1ull)       ? s[j][2] : -INFINITY;
            s[j][3] = ((whi >> (idx + 1)) & 1ull) ? s[j][3] : -INFINITY;
            rmax_lo = fmaxf(rmax_lo, fmaxf(s[j][0], s[j][1]));
            rmax_hi = fmaxf(rmax_hi, fmaxf(s[j][2], s[j][3]));
        }
        rmax_lo = fmaxf(rmax_lo, __shfl_xor_sync(0xffffffff, rmax_lo, 1));
        rmax_lo = fmaxf(rmax_lo, __shfl_xor_sync(0xffffffff, rmax_lo, 2));
        rmax_hi = fmaxf(rmax_hi, __shfl_xor_sync(0xffffffff, rmax_hi, 1));
        rmax_hi = fmaxf(rmax_hi, __shfl_xor_sync(0xffffffff, rmax_hi, 2));

        float mn_lo = fmaxf(m_lo, rmax_lo);
        float mn_hi = fmaxf(m_hi, rmax_hi);
        float safe_lo = (mn_lo > -INFINITY) ? mn_lo : 0.f;
        float safe_hi = (mn_hi > -INFINITY) ? mn_hi : 0.f;
        float al = __expf(m_lo - safe_lo);
        float ah = __expf(m_hi - safe_hi);

        float rs_lo = 0.f, rs_hi = 0.f;
#pragma unroll
        for (int j = 0; j < 8; j++) {
            s[j][0] = __expf(s[j][0] - safe_lo);
            s[j][1] = __expf(s[j][1] - safe_lo);
            s[j][2] = __expf(s[j][2] - safe_hi);
            s[j][3] = __expf(s[j][3] - safe_hi);
            rs_lo += s[j][0] + s[j][1];
            rs_hi += s[j][2] + s[j][3];
        }
        rs_lo += __shfl_xor_sync(0xffffffff, rs_lo, 1);
        rs_lo += __shfl_xor_sync(0xffffffff, rs_lo, 2);
        rs_hi += __shfl_xor_sync(0xffffffff, rs_hi, 1);
        rs_hi += __shfl_xor_sync(0xffffffff, rs_hi, 2);

        l_lo = l_lo * al + rs_lo;
        l_hi = l_hi * ah + rs_hi;
        m_lo = mn_lo;
        m_hi = mn_hi;

#pragma unroll
        for (int j = 0; j < 8; j++) {
            o[j][0] *= al; o[j][1] *= al;
            o[j][2] *= ah; o[j][3] *= ah;
        }

        // ---- O += P V : shuffle C->A frag, paired V loads ----
#pragma unroll
        for (int kc = 0; kc < 8; kc++) {
            float t0v = __shfl_sync(0xffffffffu, s[kc][0], srcA);
            float t1v = __shfl_sync(0xffffffffu, s[kc][1], srcA);
            float t2v = __shfl_sync(0xffffffffu, s[kc][2], srcA);
            float t3v = __shfl_sync(0xffffffffu, s[kc][3], srcA);
            float u0v = __shfl_sync(0xffffffffu, s[kc][0], srcB);
            float u1v = __shfl_sync(0xffffffffu, s[kc][1], srcB);
            float u2v = __shfl_sync(0xffffffffu, s[kc][2], srcB);
            float u3v = __shfl_sync(0xffffffffu, s[kc][3], srcB);
            uint32_t a[4];
            a[0] = f2tf(esel ? t1v : t0v);
            a[1] = f2tf(esel ? t3v : t2v);
            a[2] = f2tf(esel ? u1v : u0v);
            a[3] = f2tf(esel ? u3v : u2v);
            const float* vd = vbase + (size_t)(jt0 + kc) * 512;
#pragma unroll
            for (int jp = 0; jp < 4; jp++) {
                float4 vv = *(const float4*)(vd + jp * 128);
                mma_tf32(o[jp * 2],     a,
                         __float_as_uint(vv.x), __float_as_uint(vv.y));
                mma_tf32(o[jp * 2 + 1], a,
                         __float_as_uint(vv.z), __float_as_uint(vv.w));
            }
        }
    }

    // ---- epilogue: normalize, write msgs in A-pack tf32 ----
    float il_lo = (l_lo > 0.f) ? (1.0f / l_lo) : 0.f;
    float il_hi = (l_hi > 0.f) ? (1.0f / l_hi) : 0.f;
#pragma unroll
    for (int jc = 0; jc < 8; jc++) {
        float* base = Mp + (size_t)(mbq * 64 + h * 8 + jc) * 128;
#pragma unroll
        for (int e = 0; e < 2; e++) {
            int cc = 2 * qc + e;
            int la = qr * 4 + (cc & 3);
            int ix = (cc >> 2) << 1;
            base[la * 4 + ix]     = __uint_as_float(f2tf(o[jc][e]     * il_lo));
            base[la * 4 + ix + 1] = __uint_as_float(f2tf(o[jc][e + 2] * il_hi));
        }
    }
}

// ---------------------------------------------------------------------------
extern "C" void kernel_launch(void* const* d_in, const int* in_sizes, int n_in,
                              void* d_out, int out_size)
{
    (void)in_sizes; (void)n_in; (void)out_size;
    const float* x    = (const float*)d_in[0];
    const float* mask = (const float*)d_in[1];
    const float* Wq   = (const float*)d_in[2];
    const float* Wk   = (const float*)d_in[3];
    const float* Wv   = (const float*)d_in[4];
    const float* bq   = (const float*)d_in[5];
    const float* bk   = (const float*)d_in[6];
    const float* bv   = (const float*)d_in[7];
    const float* Wo   = (const float*)d_in[8];
    const float* bo   = (const float*)d_in[9];
    float* out = (float*)d_out;

    float *xp, *qp, *kp, *vp, *mp, *wqp, *wkp, *wvp, *wop;
    unsigned long long* mbp;
    cudaGetSymbolAddress((void**)&xp,  g_xp);
    cudaGetSymbolAddress((void**)&qp,  g_q);
    cudaGetSymbolAddress((void**)&kp,  g_k);
    cudaGetSymbolAddress((void**)&vp,  g_v);
    cudaGetSymbolAddress((void**)&mp,  g_m);
    cudaGetSymbolAddress((void**)&wqp, g_wq);
    cudaGetSymbolAddress((void**)&wkp, g_wk);
    cudaGetSymbolAddress((void**)&wvp, g_wv);
    cudaGetSymbolAddress((void**)&wop, g_wo);
    cudaGetSymbolAddress((void**)&mbp, g_mb);

    prep_x_kernel<<<8192, 256>>>(x, xp);
    prep_w_kernel<<<256, 256>>>(Wq, wqp, 0.125f);   // fold rsqrt(64) into Wq
    prep_w_kernel<<<256, 256>>>(Wk, wkp, 1.0f);
    prep_w_kernel<<<256, 256>>>(Wv, wvp, 1.0f);
    prep_w_kernel<<<256, 256>>>(Wo, wop, 1.0f);
    prep_mask_kernel<<<2048, 256>>>(mask, mbp);

    dim3 gg(8, 128);
    gemm_tc_kernel<3><<<gg, 128>>>(xp, wqp, bq, qp, 0.125f);  // Q (pre-scaled)
    gemm_tc_kernel<1><<<gg, 128>>>(xp, wkp, bk, kp, 1.0f);    // K pack
    gemm_tc_kernel<2><<<gg, 128>>>(xp, wvp, bv, vp, 1.0f);    // V pack

    dim3 ga(Sx / 64, Bx, Hx);   // (32, 8, 8)
    attn_tc_kernel<<<ga, 128>>>(qp, kp, vp, mbp, mp);

    gemm_tc_kernel<0><<<gg, 128>>>(mp, wop, bo, out, 1.0f);   // final projection
}

// round 7
// speedup vs baseline: 2.8295x; 2.8295x over previous
#include <cuda_runtime.h>
#include <cuda_fp16.h>
#include <math.h>
#include <stdint.h>

#define Bx   8
#define Sx   2048
#define Hx   8
#define Mh   64
#define HMx  512

// ---------------------------------------------------------------------------
// Global scratch (allocation-free rule)
// ---------------------------------------------------------------------------
__device__ float g_xp[(size_t)Bx * Sx * HMx];   // x  in A-frag pack (tf32)
__device__ float g_q [(size_t)Bx * Sx * HMx];   // Q  fp16 A-frag pack (as u32)
__device__ float g_k [(size_t)Bx * Sx * HMx];   // K  fp16 B-frag pack
__device__ float g_v [(size_t)Bx * Sx * HMx];   // V  fp16 B-frag pack
__device__ float g_m [(size_t)Bx * Sx * HMx];   // msgs in A-frag pack (tf32)
__device__ float g_wq[512 * 512];
__device__ float g_wk[512 * 512];
__device__ float g_wv[512 * 512];
__device__ float g_wo[512 * 512];
__device__ unsigned long long g_mb[(size_t)Bx * Sx * 32];  // mask bitwords

__device__ __forceinline__ uint32_t f2tf(float x) {
    uint32_t r;
    asm("cvt.rna.tf32.f32 %0, %1;" : "=r"(r) : "f"(x));
    return r;
}
// pack {lo, hi} floats into one f16x2 register (lo in low 16 bits)
__device__ __forceinline__ uint32_t h2(float lo, float hi) {
    uint32_t r;
    asm("cvt.rn.f16x2.f32 %0, %1, %2;" : "=r"(r) : "f"(hi), "f"(lo));
    return r;
}
__device__ __forceinline__ void mma_tf32(float* c, const uint32_t* a,
                                         uint32_t b0, uint32_t b1) {
    asm volatile(
        "mma.sync.aligned.m16n8k8.row.col.f32.tf32.tf32.f32 "
        "{%0,%1,%2,%3}, {%4,%5,%6,%7}, {%8,%9}, {%0,%1,%2,%3};"
        : "+f"(c[0]), "+f"(c[1]), "+f"(c[2]), "+f"(c[3])
        : "r"(a[0]), "r"(a[1]), "r"(a[2]), "r"(a[3]), "r"(b0), "r"(b1));
}
__device__ __forceinline__ void mma_f16(float* c, const uint32_t* a,
                                        uint32_t b0, uint32_t b1) {
    asm volatile(
        "mma.sync.aligned.m16n8k16.row.col.f32.f16.f16.f32 "
        "{%0,%1,%2,%3}, {%4,%5,%6,%7}, {%8,%9}, {%0,%1,%2,%3};"
        : "+f"(c[0]), "+f"(c[1]), "+f"(c[2]), "+f"(c[3])
        : "r"(a[0]), "r"(a[1]), "r"(a[2]), "r"(a[3]), "r"(b0), "r"(b1));
}

// ---------------------------------------------------------------------------
// prep: x[16384,512] -> A-pack tf32 (unchanged from R4)
// ---------------------------------------------------------------------------
__global__ void prep_x_kernel(const float* __restrict__ x, float* __restrict__ xp)
{
    int t  = blockIdx.x * 256 + threadIdx.x;
    int r  = t >> 7;
    int c4 = (t & 127) << 2;
    float4 v = *(const float4*)&x[(size_t)r * 512 + c4];
    int mb = r >> 4, rr = r & 15;
    int qrp = rr & 7, hi = rr >> 3;
    float vv[4] = {v.x, v.y, v.z, v.w};
#pragma unroll
    for (int i = 0; i < 4; i++) {
        int col = c4 + i;
        int dg = col >> 3, cc = col & 7;
        int lane = qrp * 4 + (cc & 3);
        int idx  = hi + ((cc >> 2) << 1);
        xp[(size_t)(mb * 64 + dg) * 128 + lane * 4 + idx] =
            __uint_as_float(f2tf(vv[i]));
    }
}

// ---------------------------------------------------------------------------
// prep: W[512,512] -> paired W-pack tf32 (pow2 prescale is tf32-exact)
// ---------------------------------------------------------------------------
__global__ void prep_w_kernel(const float* __restrict__ Wsrc,
                              float* __restrict__ wp, float scale)
{
    int t  = blockIdx.x * 256 + threadIdx.x;
    int k  = t >> 7;
    int c4 = (t & 127) << 2;
    float4 v = *(const float4*)&Wsrc[(size_t)k * 512 + c4];
    int dg = k >> 3, kk = k & 7;
    int s  = kk >> 2;
    float vv[4] = {v.x, v.y, v.z, v.w};
#pragma unroll
    for (int i = 0; i < 4; i++) {
        int n = c4 + i;
        int jg = n >> 3, nn = n & 7;
        int lane = nn * 4 + (kk & 3);
        wp[(size_t)dg * 4096 + (jg >> 1) * 128 + lane * 4 + (jg & 1) * 2 + s] =
            __uint_as_float(f2tf(vv[i] * scale));
    }
}

// ---------------------------------------------------------------------------
// prep: mask[B,S,S] float -> 64-bit words
// ---------------------------------------------------------------------------
__global__ void prep_mask_kernel(const float* __restrict__ mask,
                                 unsigned long long* __restrict__ mb)
{
    int warp = blockIdx.x * 8 + (threadIdx.x >> 5);
    int lane = threadIdx.x & 31;
    const float* row = mask + (size_t)warp * 2048;
    unsigned long long* dst = mb + (size_t)warp * 32;
#pragma unroll 4
    for (int w = 0; w < 32; w++) {
        float m0 = row[w * 64 + lane];
        float m1 = row[w * 64 + 32 + lane];
        unsigned b0 = __ballot_sync(0xffffffffu, m0 > 0.5f);
        unsigned b1 = __ballot_sync(0xffffffffu, m1 > 0.5f);
        if (lane == 0)
            dst[w] = ((unsigned long long)b1 << 32) | b0;
    }
}

// ---------------------------------------------------------------------------
// tf32 GEMM (R4 config: M=16/warp, grid (8,256)); fp16-pack epilogues.
// MODE: 0 = plain fp32 out, 1 = K fp16 pack, 2 = V fp16 pack, 3 = Q fp16 pack
// ---------------------------------------------------------------------------
template<int MODE>
__global__ void __launch_bounds__(128) gemm_tc_kernel(
    const float* __restrict__ Ap, const float* __restrict__ Wp,
    const float* __restrict__ bias, float* __restrict__ out, float bscale)
{
    const int w    = threadIdx.x >> 5;
    const int lane = threadIdx.x & 31;
    const int qr   = lane >> 2;
    const int qc   = lane & 3;
    const int nb   = blockIdx.x;              // 64-col block == head for K/V/Q
    const int mb   = blockIdx.y * 4 + w;      // 16-row group

    float o[8][4];
#pragma unroll
    for (int j = 0; j < 8; j++)
#pragma unroll
        for (int u = 0; u < 4; u++) o[j][u] = 0.f;

    const float* abase = Ap + (size_t)mb * 8192 + lane * 4;
    const float* wbase = Wp + (size_t)nb * 512 + lane * 4;

    for (int ck = 0; ck < 8; ck++) {
        uint32_t qa[8][4];
#pragma unroll
        for (int dd = 0; dd < 8; dd++) {
            float4 a4 = *(const float4*)(abase + (ck * 8 + dd) * 128);
            qa[dd][0] = __float_as_uint(a4.x);
            qa[dd][1] = __float_as_uint(a4.y);
            qa[dd][2] = __float_as_uint(a4.z);
            qa[dd][3] = __float_as_uint(a4.w);
        }
#pragma unroll
        for (int dd = 0; dd < 8; dd++) {
            const float* wd = wbase + (size_t)(ck * 8 + dd) * 4096;
#pragma unroll
            for (int jp = 0; jp < 4; jp++) {
                float4 wv = *(const float4*)(wd + jp * 128);
                mma_tf32(o[jp * 2],     qa[dd],
                         __float_as_uint(wv.x), __float_as_uint(wv.y));
                mma_tf32(o[jp * 2 + 1], qa[dd],
                         __float_as_uint(wv.z), __float_as_uint(wv.w));
            }
        }
    }

    const int rlo = mb * 16 + qr;
    const int n0  = nb * 64;

    if (MODE == 0) {
        const int rhi = rlo + 8;
#pragma unroll
        for (int jc = 0; jc < 8; jc++) {
            int col = n0 + jc * 8 + 2 * qc;
            float2 bb = *(const float2*)&bias[col];
            float2 lo_v = {o[jc][0] + bb.x, o[jc][1] + bb.y};
            float2 hi_v = {o[jc][2] + bb.x, o[jc][3] + bb.y};
            *(float2*)&out[(size_t)rlo * 512 + col] = lo_v;
            *(float2*)&out[(size_t)rhi * 512 + col] = hi_v;
        }
    } else if (MODE == 3) {
        // Q fp16 A-pack: off_u32 = ((mb*32 + nb*4 + jc/2)*32 + lane)*4 + reg
        // reg = (row_hi) + 2*(jc&1); u32 = half2 {e0, e1}
        uint32_t* ob = (uint32_t*)out + ((size_t)(mb * 32 + nb * 4) * 32 + lane) * 4;
#pragma unroll
        for (int jc = 0; jc < 8; jc++) {
            float2 bb = *(const float2*)&bias[n0 + jc * 8 + 2 * qc];
            bb.x *= bscale; bb.y *= bscale;
            uint32_t* base = ob + (size_t)(jc >> 1) * 128 + (jc & 1) * 2;
            base[0] = h2(o[jc][0] + bb.x, o[jc][1] + bb.y);   // rlo
            base[1] = h2(o[jc][2] + bb.x, o[jc][3] + bb.y);   // rhi
        }
    } else if (MODE == 1) {
        // K fp16 B-pack: off_u32 = (((bh*4 + jc/2)*128 + jp)*32 + lane)*4
        //                + jo*2 + (jc&1);  jo: rlo=0, rhi=1
        int b   = rlo >> 11;
        int tok = rlo & 2047;
        int jp  = tok >> 4;
        uint32_t* ob = (uint32_t*)out +
            (((size_t)(b * 8 + nb) * 4) * 128 + jp) * 128 + lane * 4;
#pragma unroll
        for (int jc = 0; jc < 8; jc++) {
            float2 bb = *(const float2*)&bias[n0 + jc * 8 + 2 * qc];
            uint32_t* base = ob + (size_t)(jc >> 1) * 16384 + (jc & 1);
            base[0] = h2(o[jc][0] + bb.x, o[jc][1] + bb.y);   // jo=0 (rlo)
            base[2] = h2(o[jc][2] + bb.x, o[jc][3] + bb.y);   // jo=1 (rhi)
        }
    } else {
        // V fp16 B-pack: off_u32 = (((bh*128 + kc)*4 + jc/2)*32 + lane_v)*4
        //                + (jc&1)*2 + reg; half index = qr&1
        int b   = rlo >> 11;
        int tok = rlo & 2047;
        int kc  = tok >> 4;          // tok%16 == qr (rlo) / qr+8 (rhi)
        int hsel = qr & 1;
        __half* ob = (__half*)((uint32_t*)out +
            (((size_t)(b * 8 + nb) * 128 + kc) * 4) * 128);
#pragma unroll
        for (int jc = 0; jc < 8; jc++) {
            float2 bb = *(const float2*)&bias[n0 + jc * 8 + 2 * qc];
            size_t jbase = (size_t)(jc >> 1) * 128;
#pragma unroll
            for (int e = 0; e < 2; e++) {
                int lane_v = (2 * qc + e) * 4 + (qr >> 1);
                size_t u32i = jbase + lane_v * 4 + (jc & 1) * 2;
                float bv = e ? bb.y : bb.x;
                ob[(u32i + 0) * 2 + hsel] = __float2half_rn(o[jc][e]     + bv);
                ob[(u32i + 1) * 2 + hsel] = __float2half_rn(o[jc][e + 2] + bv);
            }
        }
    }
}

// ---------------------------------------------------------------------------
// fp16 tensor-core flash attention, smem-free, shuffle-free P conversion.
// Block = (64 queries, b, h); 4 warps x 16 rows; key chunks of 64.
// ---------------------------------------------------------------------------
__global__ void __launch_bounds__(128) attn_tc_kernel(
    const float* __restrict__ Qp, const float* __restrict__ Kp,
    const float* __restrict__ Vp, const unsigned long long* __restrict__ mb,
    float* __restrict__ Mp)
{
    const int h  = blockIdx.z;
    const int b  = blockIdx.y;
    const int q0 = blockIdx.x * 64;
    const int tid  = threadIdx.x;
    const int w    = tid >> 5;
    const int lane = tid & 31;
    const int qr   = lane >> 2;
    const int qc   = lane & 3;

    const int mbq = b * 128 + (q0 >> 4) + w;

    // ---- Q fragments: 4 x LDG.128 (fp16 A-pack, pre-scaled), persistent ----
    uint32_t qa[4][4];
    {
        const uint4* qb = (const uint4*)((const uint32_t*)Qp +
            ((size_t)(mbq * 32 + h * 4) * 32 + lane) * 4);
#pragma unroll
        for (int d = 0; d < 4; d++) {
            uint4 a4 = qb[d * 32];
            qa[d][0] = a4.x; qa[d][1] = a4.y; qa[d][2] = a4.z; qa[d][3] = a4.w;
        }
    }

    float o[8][4];
#pragma unroll
    for (int j = 0; j < 8; j++)
#pragma unroll
        for (int u = 0; u < 4; u++) o[j][u] = 0.f;
    float m_lo = -INFINITY, m_hi = -INFINITY;
    float l_lo = 0.f, l_hi = 0.f;

    const int rlo = w * 16 + qr;
    const int rhi = rlo + 8;
    const unsigned long long* mb_lo = mb + (size_t)(b * Sx + q0 + rlo) * 32;
    const unsigned long long* mb_hi = mb + (size_t)(b * Sx + q0 + rhi) * 32;

    const size_t bh = (size_t)(b * 8 + h);
    const uint32_t* kbase = (const uint32_t*)Kp + (bh * 4) * 16384 + lane * 4;
    const uint32_t* vbase = (const uint32_t*)Vp + (bh * 128) * 512 + lane * 4;

    const int bidx0 = 2 * qc;

    for (int t0 = 0; t0 < Sx; t0 += 64) {
        const int jpt0 = t0 >> 4;   // j-pair base for K
        const int kct0 = t0 >> 4;   // 16-key group base for V

        // ---- S = Q K^T : 16 LDG.128, 32 fp16 MMAs ----
        float s[8][4];
#pragma unroll
        for (int j = 0; j < 8; j++)
#pragma unroll
            for (int u = 0; u < 4; u++) s[j][u] = 0.f;
#pragma unroll
        for (int d = 0; d < 4; d++) {
            const uint4* kd = (const uint4*)(kbase + (size_t)(d * 128 + jpt0) * 128);
#pragma unroll
            for (int jp = 0; jp < 4; jp++) {
                uint4 kv = kd[jp * 32];
                mma_f16(s[jp * 2],     qa[d], kv.x, kv.y);
                mma_f16(s[jp * 2 + 1], qa[d], kv.z, kv.w);
            }
        }

        // ---- mask (bitwords) + row max ----
        unsigned long long wlo = mb_lo[t0 >> 6];
        unsigned long long whi = mb_hi[t0 >> 6];
        float rmax_lo = -INFINITY, rmax_hi = -INFINITY;
#pragma unroll
        for (int j = 0; j < 8; j++) {
            int idx = j * 8 + bidx0;
            s[j][0] = ((wlo >> idx) & 1ull)       ? s[j][0] : -INFINITY;
            s[j][1] = ((wlo >> (idx + 1)) & 1ull) ? s[j][1] : -INFINITY;
            s[j][2] = ((whi >> idx) & 1ull)       ? s[j][2] : -INFINITY;
            s[j][3] = ((whi >> (idx + 1)) & 1ull) ? s[j][3] : -INFINITY;
            rmax_lo = fmaxf(rmax_lo, fmaxf(s[j][0], s[j][1]));
            rmax_hi = fmaxf(rmax_hi, fmaxf(s[j][2], s[j][3]));
        }
        rmax_lo = fmaxf(rmax_lo, __shfl_xor_sync(0xffffffff, rmax_lo, 1));
        rmax_lo = fmaxf(rmax_lo, __shfl_xor_sync(0xffffffff, rmax_lo, 2));
        rmax_hi = fmaxf(rmax_hi, __shfl_xor_sync(0xffffffff, rmax_hi, 1));
        rmax_hi = fmaxf(rmax_hi, __shfl_xor_sync(0xffffffff, rmax_hi, 2));

        float mn_lo = fmaxf(m_lo, rmax_lo);
        float mn_hi = fmaxf(m_hi, rmax_hi);
        float safe_lo = (mn_lo > -INFINITY) ? mn_lo : 0.f;
        float safe_hi = (mn_hi > -INFINITY) ? mn_hi : 0.f;
        float al = __expf(m_lo - safe_lo);
        float ah = __expf(m_hi - safe_hi);

        float rs_lo = 0.f, rs_hi = 0.f;
#pragma unroll
        for (int j = 0; j < 8; j++) {
            s[j][0] = __expf(s[j][0] - safe_lo);
            s[j][1] = __expf(s[j][1] - safe_lo);
            s[j][2] = __expf(s[j][2] - safe_hi);
            s[j][3] = __expf(s[j][3] - safe_hi);
            rs_lo += s[j][0] + s[j][1];
            rs_hi += s[j][2] + s[j][3];
        }
        rs_lo += __shfl_xor_sync(0xffffffff, rs_lo, 1);
        rs_lo += __shfl_xor_sync(0xffffffff, rs_lo, 2);
        rs_hi += __shfl_xor_sync(0xffffffff, rs_hi, 1);
        rs_hi += __shfl_xor_sync(0xffffffff, rs_hi, 2);

        l_lo = l_lo * al + rs_lo;
        l_hi = l_hi * ah + rs_hi;
        m_lo = mn_lo;
        m_hi = mn_hi;

#pragma unroll
        for (int j = 0; j < 8; j++) {
            o[j][0] *= al; o[j][1] *= al;
            o[j][2] *= ah; o[j][3] *= ah;
        }

        // ---- O += P V : C-frags pack natively into fp16 k16 A-frags ----
#pragma unroll
        for (int kc = 0; kc < 4; kc++) {
            uint32_t a[4];
            a[0] = h2(s[2 * kc][0],     s[2 * kc][1]);
            a[1] = h2(s[2 * kc][2],     s[2 * kc][3]);
            a[2] = h2(s[2 * kc + 1][0], s[2 * kc + 1][1]);
            a[3] = h2(s[2 * kc + 1][2], s[2 * kc + 1][3]);
            const uint4* vd = (const uint4*)(vbase + (size_t)(kct0 + kc) * 512);
#pragma unroll
            for (int jp = 0; jp < 4; jp++) {
                uint4 vv = vd[jp * 32];
                mma_f16(o[jp * 2],     a, vv.x, vv.y);
                mma_f16(o[jp * 2 + 1], a, vv.z, vv.w);
            }
        }
    }

    // ---- epilogue: normalize, write msgs in A-pack tf32 (unchanged) ----
    float il_lo = (l_lo > 0.f) ? (1.0f / l_lo) : 0.f;
    float il_hi = (l_hi > 0.f) ? (1.0f / l_hi) : 0.f;
#pragma unroll
    for (int jc = 0; jc < 8; jc++) {
        float* base = Mp + (size_t)(mbq * 64 + h * 8 + jc) * 128;
#pragma unroll
        for (int e = 0; e < 2; e++) {
            int cc = 2 * qc + e;
            int la = qr * 4 + (cc & 3);
            int ix = (cc >> 2) << 1;
            base[la * 4 + ix]     = __uint_as_float(f2tf(o[jc][e]     * il_lo));
            base[la * 4 + ix + 1] = __uint_as_float(f2tf(o[jc][e + 2] * il_hi));
        }
    }
}

// ---------------------------------------------------------------------------
extern "C" void kernel_launch(void* const* d_in, const int* in_sizes, int n_in,
                              void* d_out, int out_size)
{
    (void)in_sizes; (void)n_in; (void)out_size;
    const float* x    = (const float*)d_in[0];
    const float* mask = (const float*)d_in[1];
    const float* Wq   = (const float*)d_in[2];
    const float* Wk   = (const float*)d_in[3];
    const float* Wv   = (const float*)d_in[4];
    const float* bq   = (const float*)d_in[5];
    const float* bk   = (const float*)d_in[6];
    const float* bv   = (const float*)d_in[7];
    const float* Wo   = (const float*)d_in[8];
    const float* bo   = (const float*)d_in[9];
    float* out = (float*)d_out;

    float *xp, *qp, *kp, *vp, *mp, *wqp, *wkp, *wvp, *wop;
    unsigned long long* mbp;
    cudaGetSymbolAddress((void**)&xp,  g_xp);
    cudaGetSymbolAddress((void**)&qp,  g_q);
    cudaGetSymbolAddress((void**)&kp,  g_k);
    cudaGetSymbolAddress((void**)&vp,  g_v);
    cudaGetSymbolAddress((void**)&mp,  g_m);
    cudaGetSymbolAddress((void**)&wqp, g_wq);
    cudaGetSymbolAddress((void**)&wkp, g_wk);
    cudaGetSymbolAddress((void**)&wvp, g_wv);
    cudaGetSymbolAddress((void**)&wop, g_wo);
    cudaGetSymbolAddress((void**)&mbp, g_mb);

    prep_x_kernel<<<8192, 256>>>(x, xp);
    prep_w_kernel<<<256, 256>>>(Wq, wqp, 0.125f);   // fold rsqrt(64) into Wq
    prep_w_kernel<<<256, 256>>>(Wk, wkp, 1.0f);
    prep_w_kernel<<<256, 256>>>(Wv, wvp, 1.0f);
    prep_w_kernel<<<256, 256>>>(Wo, wop, 1.0f);
    prep_mask_kernel<<<2048, 256>>>(mask, mbp);

    dim3 gg(8, 256);    // R4 GEMM config (M=16/warp)
    gemm_tc_kernel<3><<<gg, 128>>>(xp, wqp, bq, qp, 0.125f);  // Q fp16 pack
    gemm_tc_kernel<1><<<gg, 128>>>(xp, wkp, bk, kp, 1.0f);    // K fp16 pack
    gemm_tc_kernel<2><<<gg, 128>>>(xp, wvp, bv, vp, 1.0f);    // V fp16 pack

    dim3 ga(Sx / 64, Bx, Hx);   // (32, 8, 8)
    attn_tc_kernel<<<ga, 128>>>(qp, kp, vp, mbp, mp);

    gemm_tc_kernel<0><<<gg, 128>>>(mp, wop, bo, out, 1.0f);   // final projection
}

// round 8
// speedup vs baseline: 3.2612x; 1.1526x over previous
#include <cuda_runtime.h>
#include <cuda_fp16.h>
#include <math.h>
#include <stdint.h>

#define Bx   8
#define Sx   2048
#define Hx   8
#define Mh   64
#define HMx  512

// ---------------------------------------------------------------------------
// Global scratch (allocation-free rule). All fp16 packs stored in float-sized
// buffers (only low half used where applicable).
// ---------------------------------------------------------------------------
__device__ float g_xp[(size_t)Bx * Sx * HMx / 2];   // x  fp16 A-pack
__device__ float g_q [(size_t)Bx * Sx * HMx / 2];   // Q  fp16 A-pack (pre-scaled)
__device__ float g_k [(size_t)Bx * Sx * HMx / 2];   // K  fp16 B-pack
__device__ float g_v [(size_t)Bx * Sx * HMx / 2];   // V  fp16 B-pack
__device__ float g_m [(size_t)Bx * Sx * HMx / 2];   // msgs fp16 A-pack
__device__ float g_wq[512 * 256];                    // fp16 W-packs
__device__ float g_wk[512 * 256];
__device__ float g_wv[512 * 256];
__device__ float g_wo[512 * 256];
__device__ unsigned long long g_mb[(size_t)Bx * Sx * 32];  // mask bitwords

// pack {lo, hi} floats into one f16x2 register (lo in low 16 bits)
__device__ __forceinline__ uint32_t h2(float lo, float hi) {
    uint32_t r;
    asm("cvt.rn.f16x2.f32 %0, %1, %2;" : "=r"(r) : "f"(hi), "f"(lo));
    return r;
}
__device__ __forceinline__ void mma_f16(float* c, const uint32_t* a,
                                        uint32_t b0, uint32_t b1) {
    asm volatile(
        "mma.sync.aligned.m16n8k16.row.col.f32.f16.f16.f32 "
        "{%0,%1,%2,%3}, {%4,%5,%6,%7}, {%8,%9}, {%0,%1,%2,%3};"
        : "+f"(c[0]), "+f"(c[1]), "+f"(c[2]), "+f"(c[3])
        : "r"(a[0]), "r"(a[1]), "r"(a[2]), "r"(a[3]), "r"(b0), "r"(b1));
}

// fp16 A-pack: u32 off = ((mb*32 + dk)*32 + lane)*4 + reg
//   reg = rowhi + 2*(kk>=8); lane = (row%8)*4 + ((kk&7)>>1); half = kk&1
// fp16 W/B-pack (paired jg): u32 off = ((dk*32 + jp)*32 + lane)*4 + jo*2 + s
//   b0: k=2qc,2qc+1 @ n=qr (s=0); b1: k+8 (s=1); jp=jg>>1, jo=jg&1

// ---------------------------------------------------------------------------
// prep: x[16384,512] -> fp16 A-pack
// ---------------------------------------------------------------------------
__global__ void prep_x_kernel(const float* __restrict__ x, __half* __restrict__ xp)
{
    int t  = blockIdx.x * 256 + threadIdx.x;
    int r  = t >> 7;
    int c4 = (t & 127) << 2;
    float4 v = *(const float4*)&x[(size_t)r * 512 + c4];
    int mb = r >> 4, qr = r & 7, hi = (r >> 3) & 1;
    float vv[4] = {v.x, v.y, v.z, v.w};
#pragma unroll
    for (int i = 0; i < 4; i++) {
        int c  = c4 + i;
        int dk = c >> 4, kk = c & 15;
        int reg  = hi + ((kk >> 3) << 1);
        int lane = qr * 4 + ((kk & 7) >> 1);
        size_t off = ((size_t)(mb * 32 + dk) * 32 + lane) * 4 + reg;
        xp[off * 2 + (kk & 1)] = __float2half_rn(vv[i]);
    }
}

// ---------------------------------------------------------------------------
// prep: W[512,512] -> fp16 B-pack (pow2 prescale exact)
// ---------------------------------------------------------------------------
__global__ void prep_w_kernel(const float* __restrict__ Wsrc,
                              __half* __restrict__ wp, float scale)
{
    int t  = blockIdx.x * 256 + threadIdx.x;
    int k  = t >> 7;
    int c4 = (t & 127) << 2;
    float4 v = *(const float4*)&Wsrc[(size_t)k * 512 + c4];
    int dk = k >> 4, kk = k & 15;
    int s    = kk >> 3;
    int qcw  = (kk & 7) >> 1;
    int hsel = kk & 1;
    float vv[4] = {v.x, v.y, v.z, v.w};
#pragma unroll
    for (int i = 0; i < 4; i++) {
        int n  = c4 + i;
        int jg = n >> 3;
        int lane = (n & 7) * 4 + qcw;
        size_t off = ((size_t)(dk * 32 + (jg >> 1)) * 32 + lane) * 4
                   + (jg & 1) * 2 + s;
        wp[off * 2 + hsel] = __float2half_rn(vv[i] * scale);
    }
}

// ---------------------------------------------------------------------------
// prep: mask[B,S,S] float -> 64-bit words
// ---------------------------------------------------------------------------
__global__ void prep_mask_kernel(const float* __restrict__ mask,
                                 unsigned long long* __restrict__ mb)
{
    int warp = blockIdx.x * 8 + (threadIdx.x >> 5);
    int lane = threadIdx.x & 31;
    const float* row = mask + (size_t)warp * 2048;
    unsigned long long* dst = mb + (size_t)warp * 32;
#pragma unroll 4
    for (int w = 0; w < 32; w++) {
        float m0 = row[w * 64 + lane];
        float m1 = row[w * 64 + 32 + lane];
        unsigned b0 = __ballot_sync(0xffffffffu, m0 > 0.5f);
        unsigned b1 = __ballot_sync(0xffffffffu, m1 > 0.5f);
        if (lane == 0)
            dst[w] = ((unsigned long long)b1 << 32) | b0;
    }
}

// ---------------------------------------------------------------------------
// fp16 GEMM, smem-free: C[16384,512] = A @ W + bias.
// grid (8, 256), 128 thr; warp = 16 rows x 64 cols; k16 steps.
// MODE: 0 = plain fp32 out, 1 = K fp16 pack, 2 = V fp16 pack, 3 = Q fp16 pack
// ---------------------------------------------------------------------------
template<int MODE>
__global__ void __launch_bounds__(128) gemm_f16_kernel(
    const uint32_t* __restrict__ Ap, const uint32_t* __restrict__ Wp,
    const float* __restrict__ bias, float* __restrict__ out, float bscale)
{
    const int w    = threadIdx.x >> 5;
    const int lane = threadIdx.x & 31;
    const int qr   = lane >> 2;
    const int qc   = lane & 3;
    const int nb   = blockIdx.x;              // 64-col block == head for K/V/Q
    const int mb   = blockIdx.y * 4 + w;      // 16-row group

    float o[8][4];
#pragma unroll
    for (int j = 0; j < 8; j++)
#pragma unroll
        for (int u = 0; u < 4; u++) o[j][u] = 0.f;

    const uint4* ab = (const uint4*)(Ap + (size_t)mb * 4096 + lane * 4);
    const uint4* wb = (const uint4*)(Wp + ((size_t)nb * 4 * 32 + lane) * 4);

#pragma unroll 4
    for (int dk = 0; dk < 32; dk++) {
        uint4 a4 = ab[dk * 32];
        uint32_t qa[4] = {a4.x, a4.y, a4.z, a4.w};
#pragma unroll
        for (int jp = 0; jp < 4; jp++) {
            uint4 wv = wb[dk * 1024 + jp * 32];
            mma_f16(o[jp * 2],     qa, wv.x, wv.y);
            mma_f16(o[jp * 2 + 1], qa, wv.z, wv.w);
        }
    }

    const int rlo = mb * 16 + qr;
    const int n0  = nb * 64;

    if (MODE == 0) {
        const int rhi = rlo + 8;
#pragma unroll
        for (int jc = 0; jc < 8; jc++) {
            int col = n0 + jc * 8 + 2 * qc;
            float2 bb = *(const float2*)&bias[col];
            float2 lo_v = {o[jc][0] + bb.x, o[jc][1] + bb.y};
            float2 hi_v = {o[jc][2] + bb.x, o[jc][3] + bb.y};
            *(float2*)&out[(size_t)rlo * 512 + col] = lo_v;
            *(float2*)&out[(size_t)rhi * 512 + col] = hi_v;
        }
    } else if (MODE == 3) {
        // Q fp16 A-pack
        uint32_t* ob = (uint32_t*)out + ((size_t)(mb * 32 + nb * 4) * 32 + lane) * 4;
#pragma unroll
        for (int jc = 0; jc < 8; jc++) {
            float2 bb = *(const float2*)&bias[n0 + jc * 8 + 2 * qc];
            bb.x *= bscale; bb.y *= bscale;
            uint32_t* base = ob + (size_t)(jc >> 1) * 128 + (jc & 1) * 2;
            base[0] = h2(o[jc][0] + bb.x, o[jc][1] + bb.y);   // rlo
            base[1] = h2(o[jc][2] + bb.x, o[jc][3] + bb.y);   // rhi
        }
    } else if (MODE == 1) {
        // K fp16 B-pack
        int b   = rlo >> 11;
        int tok = rlo & 2047;
        int jp  = tok >> 4;
        uint32_t* ob = (uint32_t*)out +
            (((size_t)(b * 8 + nb) * 4) * 128 + jp) * 128 + lane * 4;
#pragma unroll
        for (int jc = 0; jc < 8; jc++) {
            float2 bb = *(const float2*)&bias[n0 + jc * 8 + 2 * qc];
            uint32_t* base = ob + (size_t)(jc >> 1) * 16384 + (jc & 1);
            base[0] = h2(o[jc][0] + bb.x, o[jc][1] + bb.y);   // jo=0 (rlo)
            base[2] = h2(o[jc][2] + bb.x, o[jc][3] + bb.y);   // jo=1 (rhi)
        }
    } else {
        // V fp16 B-pack
        int b   = rlo >> 11;
        int tok = rlo & 2047;
        int kc  = tok >> 4;
        int hsel = qr & 1;
        __half* ob = (__half*)((uint32_t*)out +
            (((size_t)(b * 8 + nb) * 128 + kc) * 4) * 128);
#pragma unroll
        for (int jc = 0; jc < 8; jc++) {
            float2 bb = *(const float2*)&bias[n0 + jc * 8 + 2 * qc];
            size_t jbase = (size_t)(jc >> 1) * 128;
#pragma unroll
            for (int e = 0; e < 2; e++) {
                int lane_v = (2 * qc + e) * 4 + (qr >> 1);
                size_t u32i = jbase + lane_v * 4 + (jc & 1) * 2;
                float bv = e ? bb.y : bb.x;
                ob[(u32i + 0) * 2 + hsel] = __float2half_rn(o[jc][e]     + bv);
                ob[(u32i + 1) * 2 + hsel] = __float2half_rn(o[jc][e + 2] + bv);
            }
        }
    }
}

// ---------------------------------------------------------------------------
// fp16 tensor-core flash attention (R6 mainloop, fp16 msgs epilogue).
// Block = (64 queries, b, h); 4 warps x 16 rows; key chunks of 64.
// ---------------------------------------------------------------------------
__global__ void __launch_bounds__(128) attn_tc_kernel(
    const float* __restrict__ Qp, const float* __restrict__ Kp,
    const float* __restrict__ Vp, const unsigned long long* __restrict__ mb,
    float* __restrict__ Mp)
{
    const int h  = blockIdx.z;
    const int b  = blockIdx.y;
    const int q0 = blockIdx.x * 64;
    const int tid  = threadIdx.x;
    const int w    = tid >> 5;
    const int lane = tid & 31;
    const int qr   = lane >> 2;
    const int qc   = lane & 3;

    const int mbq = b * 128 + (q0 >> 4) + w;

    // ---- Q fragments: 4 x LDG.128 (fp16 A-pack, pre-scaled), persistent ----
    uint32_t qa[4][4];
    {
        const uint4* qb = (const uint4*)((const uint32_t*)Qp +
            ((size_t)(mbq * 32 + h * 4) * 32 + lane) * 4);
#pragma unroll
        for (int d = 0; d < 4; d++) {
            uint4 a4 = qb[d * 32];
            qa[d][0] = a4.x; qa[d][1] = a4.y; qa[d][2] = a4.z; qa[d][3] = a4.w;
        }
    }

    float o[8][4];
#pragma unroll
    for (int j = 0; j < 8; j++)
#pragma unroll
        for (int u = 0; u < 4; u++) o[j][u] = 0.f;
    float m_lo = -INFINITY, m_hi = -INFINITY;
    float l_lo = 0.f, l_hi = 0.f;

    const int rlo = w * 16 + qr;
    const int rhi = rlo + 8;
    const unsigned long long* mb_lo = mb + (size_t)(b * Sx + q0 + rlo) * 32;
    const unsigned long long* mb_hi = mb + (size_t)(b * Sx + q0 + rhi) * 32;

    const size_t bh = (size_t)(b * 8 + h);
    const uint32_t* kbase = (const uint32_t*)Kp + (bh * 4) * 16384 + lane * 4;
    const uint32_t* vbase = (const uint32_t*)Vp + (bh * 128) * 512 + lane * 4;

    const int bidx0 = 2 * qc;

    for (int t0 = 0; t0 < Sx; t0 += 64) {
        const int jpt0 = t0 >> 4;
        const int kct0 = t0 >> 4;

        // ---- S = Q K^T : 16 LDG.128, 32 fp16 MMAs ----
        float s[8][4];
#pragma unroll
        for (int j = 0; j < 8; j++)
#pragma unroll
            for (int u = 0; u < 4; u++) s[j][u] = 0.f;
#pragma unroll
        for (int d = 0; d < 4; d++) {
            const uint4* kd = (const uint4*)(kbase + (size_t)(d * 128 + jpt0) * 128);
#pragma unroll
            for (int jp = 0; jp < 4; jp++) {
                uint4 kv = kd[jp * 32];
                mma_f16(s[jp * 2],     qa[d], kv.x, kv.y);
                mma_f16(s[jp * 2 + 1], qa[d], kv.z, kv.w);
            }
        }

        // ---- mask (bitwords) + row max ----
        unsigned long long wlo = mb_lo[t0 >> 6];
        unsigned long long whi = mb_hi[t0 >> 6];
        float rmax_lo = -INFINITY, rmax_hi = -INFINITY;
#pragma unroll
        for (int j = 0; j < 8; j++) {
            int idx = j * 8 + bidx0;
            s[j][0] = ((wlo >> idx) & 1ull)       ? s[j][0] : -INFINITY;
            s[j][1] = ((wlo >> (idx + 1)) & 1ull) ? s[j][1] : -INFINITY;
            s[j][2] = ((whi >> idx) & 1ull)       ? s[j][2] : -INFINITY;
            s[j][3] = ((whi >> (idx + 1)) & 1ull) ? s[j][3] : -INFINITY;
            rmax_lo = fmaxf(rmax_lo, fmaxf(s[j][0], s[j][1]));
            rmax_hi = fmaxf(rmax_hi, fmaxf(s[j][2], s[j][3]));
        }
        rmax_lo = fmaxf(rmax_lo, __shfl_xor_sync(0xffffffff, rmax_lo, 1));
        rmax_lo = fmaxf(rmax_lo, __shfl_xor_sync(0xffffffff, rmax_lo, 2));
        rmax_hi = fmaxf(rmax_hi, __shfl_xor_sync(0xffffffff, rmax_hi, 1));
        rmax_hi = fmaxf(rmax_hi, __shfl_xor_sync(0xffffffff, rmax_hi, 2));

        float mn_lo = fmaxf(m_lo, rmax_lo);
        float mn_hi = fmaxf(m_hi, rmax_hi);
        float safe_lo = (mn_lo > -INFINITY) ? mn_lo : 0.f;
        float safe_hi = (mn_hi > -INFINITY) ? mn_hi : 0.f;
        float al = __expf(m_lo - safe_lo);
        float ah = __expf(m_hi - safe_hi);

        float rs_lo = 0.f, rs_hi = 0.f;
#pragma unroll
        for (int j = 0; j < 8; j++) {
            s[j][0] = __expf(s[j][0] - safe_lo);
            s[j][1] = __expf(s[j][1] - safe_lo);
            s[j][2] = __expf(s[j][2] - safe_hi);
            s[j][3] = __expf(s[j][3] - safe_hi);
            rs_lo += s[j][0] + s[j][1];
            rs_hi += s[j][2] + s[j][3];
        }
        rs_lo += __shfl_xor_sync(0xffffffff, rs_lo, 1);
        rs_lo += __shfl_xor_sync(0xffffffff, rs_lo, 2);
        rs_hi += __shfl_xor_sync(0xffffffff, rs_hi, 1);
        rs_hi += __shfl_xor_sync(0xffffffff, rs_hi, 2);

        l_lo = l_lo * al + rs_lo;
        l_hi = l_hi * ah + rs_hi;
        m_lo = mn_lo;
        m_hi = mn_hi;

#pragma unroll
        for (int j = 0; j < 8; j++) {
            o[j][0] *= al; o[j][1] *= al;
            o[j][2] *= ah; o[j][3] *= ah;
        }

        // ---- O += P V : C-frags pack natively into fp16 k16 A-frags ----
#pragma unroll
        for (int kc = 0; kc < 4; kc++) {
            uint32_t a[4];
            a[0] = h2(s[2 * kc][0],     s[2 * kc][1]);
            a[1] = h2(s[2 * kc][2],     s[2 * kc][3]);
            a[2] = h2(s[2 * kc + 1][0], s[2 * kc + 1][1]);
            a[3] = h2(s[2 * kc + 1][2], s[2 * kc + 1][3]);
            const uint4* vd = (const uint4*)(vbase + (size_t)(kct0 + kc) * 512);
#pragma unroll
            for (int jp = 0; jp < 4; jp++) {
                uint4 vv = vd[jp * 32];
                mma_f16(o[jp * 2],     a, vv.x, vv.y);
                mma_f16(o[jp * 2 + 1], a, vv.z, vv.w);
            }
        }
    }

    // ---- epilogue: normalize, write msgs in fp16 A-pack ----
    float il_lo = (l_lo > 0.f) ? (1.0f / l_lo) : 0.f;
    float il_hi = (l_hi > 0.f) ? (1.0f / l_hi) : 0.f;
    uint32_t* ob = (uint32_t*)Mp + ((size_t)(mbq * 32 + h * 4) * 32 + lane) * 4;
#pragma unroll
    for (int jc = 0; jc < 8; jc++) {
        uint32_t* base = ob + (size_t)(jc >> 1) * 128 + (jc & 1) * 2;
        base[0] = h2(o[jc][0] * il_lo, o[jc][1] * il_lo);
        base[1] = h2(o[jc][2] * il_hi, o[jc][3] * il_hi);
    }
}

// ---------------------------------------------------------------------------
extern "C" void kernel_launch(void* const* d_in, const int* in_sizes, int n_in,
                              void* d_out, int out_size)
{
    (void)in_sizes; (void)n_in; (void)out_size;
    const float* x    = (const float*)d_in[0];
    const float* mask = (const float*)d_in[1];
    const float* Wq   = (const float*)d_in[2];
    const float* Wk   = (const float*)d_in[3];
    const float* Wv   = (const float*)d_in[4];
    const float* bq   = (const float*)d_in[5];
    const float* bk   = (const float*)d_in[6];
    const float* bv   = (const float*)d_in[7];
    const float* Wo   = (const float*)d_in[8];
    const float* bo   = (const float*)d_in[9];
    float* out = (float*)d_out;

    float *xp, *qp, *kp, *vp, *mp, *wqp, *wkp, *wvp, *wop;
    unsigned long long* mbp;
    cudaGetSymbolAddress((void**)&xp,  g_xp);
    cudaGetSymbolAddress((void**)&qp,  g_q);
    cudaGetSymbolAddress((void**)&kp,  g_k);
    cudaGetSymbolAddress((void**)&vp,  g_v);
    cudaGetSymbolAddress((void**)&mp,  g_m);
    cudaGetSymbolAddress((void**)&wqp, g_wq);
    cudaGetSymbolAddress((void**)&wkp, g_wk);
    cudaGetSymbolAddress((void**)&wvp, g_wv);
    cudaGetSymbolAddress((void**)&wop, g_wo);
    cudaGetSymbolAddress((void**)&mbp, g_mb);

    prep_x_kernel<<<8192, 256>>>(x, (__half*)xp);
    prep_w_kernel<<<256, 256>>>(Wq, (__half*)wqp, 0.125f);  // fold rsqrt(64)
    prep_w_kernel<<<256, 256>>>(Wk, (__half*)wkp, 1.0f);
    prep_w_kernel<<<256, 256>>>(Wv, (__half*)wvp, 1.0f);
    prep_w_kernel<<<256, 256>>>(Wo, (__half*)wop, 1.0f);
    prep_mask_kernel<<<2048, 256>>>(mask, mbp);

    dim3 gg(8, 256);
    gemm_f16_kernel<3><<<gg, 128>>>((const uint32_t*)xp, (const uint32_t*)wqp, bq, qp, 0.125f);
    gemm_f16_kernel<1><<<gg, 128>>>((const uint32_t*)xp, (const uint32_t*)wkp, bk, kp, 1.0f);
    gemm_f16_kernel<2><<<gg, 128>>>((const uint32_t*)xp, (const uint32_t*)wvp, bv, vp, 1.0f);

    dim3 ga(Sx / 64, Bx, Hx);   // (32, 8, 8)
    attn_tc_kernel<<<ga, 128>>>(qp, kp, vp, mbp, mp);

    gemm_f16_kernel<0><<<gg, 128>>>((const uint32_t*)mp, (const uint32_t*)wop, bo, out, 1.0f);
}

// round 9
// speedup vs baseline: 3.7683x; 1.1555x over previous
#include <cuda_runtime.h>
#include <cuda_fp16.h>
#include <math.h>
#include <stdint.h>

#define Bx   8
#define Sx   2048
#define Hx   8
#define Mh   64
#define HMx  512

#define LOG2E 1.4426950408889634f
#define ONES2 0x3C003C00u

// ---------------------------------------------------------------------------
// Global scratch (allocation-free rule)
// ---------------------------------------------------------------------------
__device__ float g_xp[(size_t)Bx * Sx * HMx / 2];   // x  fp16 A-pack
__device__ float g_q [(size_t)Bx * Sx * HMx / 2];   // Q  fp16 A-pack (pre-scaled)
__device__ float g_k [(size_t)Bx * Sx * HMx / 2];   // K  fp16 B-pack
__device__ float g_v [(size_t)Bx * Sx * HMx / 2];   // V  fp16 B-pack
__device__ float g_m [(size_t)Bx * Sx * HMx / 2];   // msgs fp16 A-pack
__device__ float g_wq[512 * 256];                    // fp16 W-packs
__device__ float g_wk[512 * 256];
__device__ float g_wv[512 * 256];
__device__ float g_wo[512 * 256];
__device__ unsigned long long g_mb[(size_t)Bx * Sx * 32];  // mask bitwords

__device__ __forceinline__ uint32_t h2(float lo, float hi) {
    uint32_t r;
    asm("cvt.rn.f16x2.f32 %0, %1, %2;" : "=r"(r) : "f"(hi), "f"(lo));
    return r;
}
__device__ __forceinline__ uint32_t ex2h2(uint32_t x) {
    uint32_t r;
    asm("ex2.approx.f16x2 %0, %1;" : "=r"(r) : "r"(x));
    return r;
}
__device__ __forceinline__ void mma_f16(float* c, const uint32_t* a,
                                        uint32_t b0, uint32_t b1) {
    asm volatile(
        "mma.sync.aligned.m16n8k16.row.col.f32.f16.f16.f32 "
        "{%0,%1,%2,%3}, {%4,%5,%6,%7}, {%8,%9}, {%0,%1,%2,%3};"
        : "+f"(c[0]), "+f"(c[1]), "+f"(c[2]), "+f"(c[3])
        : "r"(a[0]), "r"(a[1]), "r"(a[2]), "r"(a[3]), "r"(b0), "r"(b1));
}

// ---------------------------------------------------------------------------
// Fused prep: blocks [0,8192) x->A-pack, [8192,9216) W->B-pack, rest mask bits
// ---------------------------------------------------------------------------
__global__ void prep_all_kernel(
    const float* __restrict__ x, const float* __restrict__ mask,
    const float* __restrict__ Wq, const float* __restrict__ Wk,
    const float* __restrict__ Wv, const float* __restrict__ Wo,
    __half* __restrict__ xp,
    __half* __restrict__ wq, __half* __restrict__ wk,
    __half* __restrict__ wv, __half* __restrict__ wo,
    unsigned long long* __restrict__ mb)
{
    int bid = blockIdx.x;
    if (bid < 8192) {
        // ---- x[16384,512] -> fp16 A-pack ----
        int t  = bid * 256 + threadIdx.x;
        int r  = t >> 7;
        int c4 = (t & 127) << 2;
        float4 v = *(const float4*)&x[(size_t)r * 512 + c4];
        int mbr = r >> 4, qr = r & 7, hi = (r >> 3) & 1;
        float vv[4] = {v.x, v.y, v.z, v.w};
#pragma unroll
        for (int i = 0; i < 4; i++) {
            int c  = c4 + i;
            int dk = c >> 4, kk = c & 15;
            int reg  = hi + ((kk >> 3) << 1);
            int lane = qr * 4 + ((kk & 7) >> 1);
            size_t off = ((size_t)(mbr * 32 + dk) * 32 + lane) * 4 + reg;
            xp[off * 2 + (kk & 1)] = __float2half_rn(vv[i]);
        }
    } else if (bid < 9216) {
        // ---- W[512,512] -> fp16 B-pack ----
        int wi = (bid - 8192) >> 8;
        const float* Wsrc = (wi == 0) ? Wq : (wi == 1) ? Wk : (wi == 2) ? Wv : Wo;
        __half* wp        = (wi == 0) ? wq : (wi == 1) ? wk : (wi == 2) ? wv : wo;
        float scale       = (wi == 0) ? 0.125f : 1.0f;   // fold rsqrt(64) into Wq
        int t  = ((bid - 8192) & 255) * 256 + threadIdx.x;
        int k  = t >> 7;
        int c4 = (t & 127) << 2;
        float4 v = *(const float4*)&Wsrc[(size_t)k * 512 + c4];
        int dk = k >> 4, kk = k & 15;
        int s    = kk >> 3;
        int qcw  = (kk & 7) >> 1;
        int hsel = kk & 1;
        float vv[4] = {v.x, v.y, v.z, v.w};
#pragma unroll
        for (int i = 0; i < 4; i++) {
            int n  = c4 + i;
            int jg = n >> 3;
            int lane = (n & 7) * 4 + qcw;
            size_t off = ((size_t)(dk * 32 + (jg >> 1)) * 32 + lane) * 4
                       + (jg & 1) * 2 + s;
            wp[off * 2 + hsel] = __float2half_rn(vv[i] * scale);
        }
    } else {
        // ---- mask[B,S,S] -> bitwords ----
        int warp = (bid - 9216) * 8 + (threadIdx.x >> 5);
        int lane = threadIdx.x & 31;
        const float* row = mask + (size_t)warp * 2048;
        unsigned long long* dst = mb + (size_t)warp * 32;
#pragma unroll 4
        for (int w = 0; w < 32; w++) {
            float m0 = row[w * 64 + lane];
            float m1 = row[w * 64 + 32 + lane];
            unsigned b0 = __ballot_sync(0xffffffffu, m0 > 0.5f);
            unsigned b1 = __ballot_sync(0xffffffffu, m1 > 0.5f);
            if (lane == 0)
                dst[w] = ((unsigned long long)b1 << 32) | b0;
        }
    }
}

// ---------------------------------------------------------------------------
// fp16 GEMM, smem-free, M=32 per warp (2 row-tiles share W frags).
// grid (8, 128), 128 thr. MODE: 0=fp32 out, 1=K pack, 2=V pack, 3=Q pack
// ---------------------------------------------------------------------------
template<int MODE>
__global__ void __launch_bounds__(128) gemm_f16_kernel(
    const uint32_t* __restrict__ Ap, const uint32_t* __restrict__ Wp,
    const float* __restrict__ bias, float* __restrict__ out, float bscale)
{
    const int w    = threadIdx.x >> 5;
    const int lane = threadIdx.x & 31;
    const int qr   = lane >> 2;
    const int qc   = lane & 3;
    const int nb   = blockIdx.x;              // 64-col block == head for K/V/Q
    const int mb0  = blockIdx.y * 8 + w * 2;  // first 16-row group of warp

    float o[2][8][4];
#pragma unroll
    for (int rt = 0; rt < 2; rt++)
#pragma unroll
        for (int j = 0; j < 8; j++)
#pragma unroll
            for (int u = 0; u < 4; u++) o[rt][j][u] = 0.f;

    const uint4* ab = (const uint4*)(Ap + (size_t)mb0 * 4096 + lane * 4);
    const uint4* wb = (const uint4*)(Wp + ((size_t)nb * 4 * 32 + lane) * 4);

#pragma unroll 4
    for (int dk = 0; dk < 32; dk++) {
        uint4 a0 = ab[dk * 32];
        uint4 a1 = ab[dk * 32 + 1024];
        uint32_t qa0[4] = {a0.x, a0.y, a0.z, a0.w};
        uint32_t qa1[4] = {a1.x, a1.y, a1.z, a1.w};
#pragma unroll
        for (int jp = 0; jp < 4; jp++) {
            uint4 wv = wb[dk * 1024 + jp * 32];
            mma_f16(o[0][jp * 2],     qa0, wv.x, wv.y);
            mma_f16(o[0][jp * 2 + 1], qa0, wv.z, wv.w);
            mma_f16(o[1][jp * 2],     qa1, wv.x, wv.y);
            mma_f16(o[1][jp * 2 + 1], qa1, wv.z, wv.w);
        }
    }

    const int n0 = nb * 64;

#pragma unroll
    for (int rt = 0; rt < 2; rt++) {
        const int mb  = mb0 + rt;
        const int rlo = mb * 16 + qr;

        if (MODE == 0) {
            const int rhi = rlo + 8;
#pragma unroll
            for (int jc = 0; jc < 8; jc++) {
                int col = n0 + jc * 8 + 2 * qc;
                float2 bb = *(const float2*)&bias[col];
                float2 lo_v = {o[rt][jc][0] + bb.x, o[rt][jc][1] + bb.y};
                float2 hi_v = {o[rt][jc][2] + bb.x, o[rt][jc][3] + bb.y};
                *(float2*)&out[(size_t)rlo * 512 + col] = lo_v;
                *(float2*)&out[(size_t)rhi * 512 + col] = hi_v;
            }
        } else if (MODE == 3) {
            uint32_t* ob = (uint32_t*)out + ((size_t)(mb * 32 + nb * 4) * 32 + lane) * 4;
#pragma unroll
            for (int jc = 0; jc < 8; jc++) {
                float2 bb = *(const float2*)&bias[n0 + jc * 8 + 2 * qc];
                bb.x *= bscale; bb.y *= bscale;
                uint32_t* base = ob + (size_t)(jc >> 1) * 128 + (jc & 1) * 2;
                base[0] = h2(o[rt][jc][0] + bb.x, o[rt][jc][1] + bb.y);
                base[1] = h2(o[rt][jc][2] + bb.x, o[rt][jc][3] + bb.y);
            }
        } else if (MODE == 1) {
            int b   = rlo >> 11;
            int tok = rlo & 2047;
            int jp  = tok >> 4;
            uint32_t* ob = (uint32_t*)out +
                (((size_t)(b * 8 + nb) * 4) * 128 + jp) * 128 + lane * 4;
#pragma unroll
            for (int jc = 0; jc < 8; jc++) {
                float2 bb = *(const float2*)&bias[n0 + jc * 8 + 2 * qc];
                uint32_t* base = ob + (size_t)(jc >> 1) * 16384 + (jc & 1);
                base[0] = h2(o[rt][jc][0] + bb.x, o[rt][jc][1] + bb.y);
                base[2] = h2(o[rt][jc][2] + bb.x, o[rt][jc][3] + bb.y);
            }
        } else {
            int b   = rlo >> 11;
            int tok = rlo & 2047;
            int kc  = tok >> 4;
            int hsel = qr & 1;
            __half* ob = (__half*)((uint32_t*)out +
                (((size_t)(b * 8 + nb) * 128 + kc) * 4) * 128);
#pragma unroll
            for (int jc = 0; jc < 8; jc++) {
                float2 bb = *(const float2*)&bias[n0 + jc * 8 + 2 * qc];
                size_t jbase = (size_t)(jc >> 1) * 128;
#pragma unroll
                for (int e = 0; e < 2; e++) {
                    int lane_v = (2 * qc + e) * 4 + (qr >> 1);
                    size_t u32i = jbase + lane_v * 4 + (jc & 1) * 2;
                    float bv = e ? bb.y : bb.x;
                    ob[(u32i + 0) * 2 + hsel] = __float2half_rn(o[rt][jc][e]     + bv);
                    ob[(u32i + 1) * 2 + hsel] = __float2half_rn(o[rt][jc][e + 2] + bv);
                }
            }
        }
    }
}

// ---------------------------------------------------------------------------
// fp16 flash attention: f16x2 exp, tensor-core row sums.
// Block = (64 queries, b, h); 4 warps x 16 rows; key chunks of 64.
// ---------------------------------------------------------------------------
__global__ void __launch_bounds__(128) attn_tc_kernel(
    const float* __restrict__ Qp, const float* __restrict__ Kp,
    const float* __restrict__ Vp, const unsigned long long* __restrict__ mb,
    float* __restrict__ Mp)
{
    const int h  = blockIdx.z;
    const int b  = blockIdx.y;
    const int q0 = blockIdx.x * 64;
    const int tid  = threadIdx.x;
    const int w    = tid >> 5;
    const int lane = tid & 31;
    const int qr   = lane >> 2;
    const int qc   = lane & 3;

    const int mbq = b * 128 + (q0 >> 4) + w;

    // ---- Q fragments: 4 x LDG.128 (fp16 A-pack, pre-scaled), persistent ----
    uint32_t qa[4][4];
    {
        const uint4* qb = (const uint4*)((const uint32_t*)Qp +
            ((size_t)(mbq * 32 + h * 4) * 32 + lane) * 4);
#pragma unroll
        for (int d = 0; d < 4; d++) {
            uint4 a4 = qb[d * 32];
            qa[d][0] = a4.x; qa[d][1] = a4.y; qa[d][2] = a4.z; qa[d][3] = a4.w;
        }
    }

    float o[8][4];
#pragma unroll
    for (int j = 0; j < 8; j++)
#pragma unroll
        for (int u = 0; u < 4; u++) o[j][u] = 0.f;
    float osum[4] = {0.f, 0.f, 0.f, 0.f};    // tensor-core row sums of P
    float m_lo = -INFINITY, m_hi = -INFINITY;

    const int rlo = w * 16 + qr;
    const int rhi = rlo + 8;
    const unsigned long long* mb_lo = mb + (size_t)(b * Sx + q0 + rlo) * 32;
    const unsigned long long* mb_hi = mb + (size_t)(b * Sx + q0 + rhi) * 32;

    const size_t bh = (size_t)(b * 8 + h);
    const uint32_t* kbase = (const uint32_t*)Kp + (bh * 4) * 16384 + lane * 4;
    const uint32_t* vbase = (const uint32_t*)Vp + (bh * 128) * 512 + lane * 4;

    const int bidx0 = 2 * qc;

    for (int t0 = 0; t0 < Sx; t0 += 64) {
        const int jpt0 = t0 >> 4;

        // ---- S = Q K^T : 16 LDG.128, 32 fp16 MMAs ----
        float s[8][4];
#pragma unroll
        for (int j = 0; j < 8; j++)
#pragma unroll
            for (int u = 0; u < 4; u++) s[j][u] = 0.f;
#pragma unroll
        for (int d = 0; d < 4; d++) {
            const uint4* kd = (const uint4*)(kbase + (size_t)(d * 128 + jpt0) * 128);
#pragma unroll
            for (int jp = 0; jp < 4; jp++) {
                uint4 kv = kd[jp * 32];
                mma_f16(s[jp * 2],     qa[d], kv.x, kv.y);
                mma_f16(s[jp * 2 + 1], qa[d], kv.z, kv.w);
            }
        }

        // ---- mask (bitwords) + row max ----
        unsigned long long wlo = mb_lo[t0 >> 6];
        unsigned long long whi = mb_hi[t0 >> 6];
        float rmax_lo = -INFINITY, rmax_hi = -INFINITY;
#pragma unroll
        for (int j = 0; j < 8; j++) {
            int idx = j * 8 + bidx0;
            s[j][0] = ((wlo >> idx) & 1ull)       ? s[j][0] : -INFINITY;
            s[j][1] = ((wlo >> (idx + 1)) & 1ull) ? s[j][1] : -INFINITY;
            s[j][2] = ((whi >> idx) & 1ull)       ? s[j][2] : -INFINITY;
            s[j][3] = ((whi >> (idx + 1)) & 1ull) ? s[j][3] : -INFINITY;
            rmax_lo = fmaxf(rmax_lo, fmaxf(s[j][0], s[j][1]));
            rmax_hi = fmaxf(rmax_hi, fmaxf(s[j][2], s[j][3]));
        }
        rmax_lo = fmaxf(rmax_lo, __shfl_xor_sync(0xffffffff, rmax_lo, 1));
        rmax_lo = fmaxf(rmax_lo, __shfl_xor_sync(0xffffffff, rmax_lo, 2));
        rmax_hi = fmaxf(rmax_hi, __shfl_xor_sync(0xffffffff, rmax_hi, 1));
        rmax_hi = fmaxf(rmax_hi, __shfl_xor_sync(0xffffffff, rmax_hi, 2));

        float mn_lo = fmaxf(m_lo, rmax_lo);
        float mn_hi = fmaxf(m_hi, rmax_hi);
        float safe_lo = (mn_lo > -INFINITY) ? mn_lo : 0.f;
        float safe_hi = (mn_hi > -INFINITY) ? mn_hi : 0.f;
        float al = __expf(m_lo - safe_lo);
        float ah = __expf(m_hi - safe_hi);
        m_lo = mn_lo;
        m_hi = mn_hi;

        // ---- P = exp2((s - m)*log2e) directly in f16x2 ----
        float clo = safe_lo * LOG2E;
        float chi = safe_hi * LOG2E;
        uint32_t p[8][2];
#pragma unroll
        for (int j = 0; j < 8; j++) {
            float t0f = fmaf(s[j][0], LOG2E, -clo);
            float t1f = fmaf(s[j][1], LOG2E, -clo);
            float t2f = fmaf(s[j][2], LOG2E, -chi);
            float t3f = fmaf(s[j][3], LOG2E, -chi);
            p[j][0] = ex2h2(h2(t0f, t1f));
            p[j][1] = ex2h2(h2(t2f, t3f));
        }

        // ---- rescale O and row-sum accumulators ----
#pragma unroll
        for (int j = 0; j < 8; j++) {
            o[j][0] *= al; o[j][1] *= al;
            o[j][2] *= ah; o[j][3] *= ah;
        }
        osum[0] *= al; osum[1] *= al;
        osum[2] *= ah; osum[3] *= ah;

        // ---- O += P V ; row sums via ones-MMA ----
#pragma unroll
        for (int kc = 0; kc < 4; kc++) {
            uint32_t a[4];
            a[0] = p[2 * kc][0];
            a[1] = p[2 * kc][1];
            a[2] = p[2 * kc + 1][0];
            a[3] = p[2 * kc + 1][1];
            const uint4* vd = (const uint4*)(vbase + (size_t)(jpt0 + kc) * 512);
#pragma unroll
            for (int jp = 0; jp < 4; jp++) {
                uint4 vv = vd[jp * 32];
                mma_f16(o[jp * 2],     a, vv.x, vv.y);
                mma_f16(o[jp * 2 + 1], a, vv.z, vv.w);
            }
            mma_f16(osum, a, ONES2, ONES2);
        }
    }

    // ---- epilogue: normalize, write msgs in fp16 A-pack ----
    float il_lo = (osum[0] > 0.f) ? (1.0f / osum[0]) : 0.f;
    float il_hi = (osum[2] > 0.f) ? (1.0f / osum[2]) : 0.f;
    uint32_t* ob = (uint32_t*)Mp + ((size_t)(mbq * 32 + h * 4) * 32 + lane) * 4;
#pragma unroll
    for (int jc = 0; jc < 8; jc++) {
        uint32_t* base = ob + (size_t)(jc >> 1) * 128 + (jc & 1) * 2;
        base[0] = h2(o[jc][0] * il_lo, o[jc][1] * il_lo);
        base[1] = h2(o[jc][2] * il_hi, o[jc][3] * il_hi);
    }
}

// ---------------------------------------------------------------------------
extern "C" void kernel_launch(void* const* d_in, const int* in_sizes, int n_in,
                              void* d_out, int out_size)
{
    (void)in_sizes; (void)n_in; (void)out_size;
    const float* x    = (const float*)d_in[0];
    const float* mask = (const float*)d_in[1];
    const float* Wq   = (const float*)d_in[2];
    const float* Wk   = (const float*)d_in[3];
    const float* Wv   = (const float*)d_in[4];
    const float* bq   = (const float*)d_in[5];
    const float* bk   = (const float*)d_in[6];
    const float* bv   = (const float*)d_in[7];
    const float* Wo   = (const float*)d_in[8];
    const float* bo   = (const float*)d_in[9];
    float* out = (float*)d_out;

    float *xp, *qp, *kp, *vp, *mp, *wqp, *wkp, *wvp, *wop;
    unsigned long long* mbp;
    cudaGetSymbolAddress((void**)&xp,  g_xp);
    cudaGetSymbolAddress((void**)&qp,  g_q);
    cudaGetSymbolAddress((void**)&kp,  g_k);
    cudaGetSymbolAddress((void**)&vp,  g_v);
    cudaGetSymbolAddress((void**)&mp,  g_m);
    cudaGetSymbolAddress((void**)&wqp, g_wq);
    cudaGetSymbolAddress((void**)&wkp, g_wk);
    cudaGetSymbolAddress((void**)&wvp, g_wv);
    cudaGetSymbolAddress((void**)&wop, g_wo);
    cudaGetSymbolAddress((void**)&mbp, g_mb);

    prep_all_kernel<<<11264, 256>>>(x, mask, Wq, Wk, Wv, Wo,
                                    (__half*)xp, (__half*)wqp, (__half*)wkp,
                                    (__half*)wvp, (__half*)wop, mbp);

    dim3 gg(8, 128);
    gemm_f16_kernel<3><<<gg, 128>>>((const uint32_t*)xp, (const uint32_t*)wqp, bq, qp, 0.125f);
    gemm_f16_kernel<1><<<gg, 128>>>((const uint32_t*)xp, (const uint32_t*)wkp, bk, kp, 1.0f);
    gemm_f16_kernel<2><<<gg, 128>>>((const uint32_t*)xp, (const uint32_t*)wvp, bv, vp, 1.0f);

    dim3 ga(Sx / 64, Bx, Hx);   // (32, 8, 8)
    attn_tc_kernel<<<ga, 128>>>(qp, kp, vp, mbp, mp);

    gemm_f16_kernel<0><<<gg, 128>>>((const uint32_t*)mp, (const uint32_t*)wop, bo, out, 1.0f);
}

// round 10
// speedup vs baseline: 4.4727x; 1.1869x over previous
#include <cuda_runtime.h>
#include <cuda_fp16.h>
#include <math.h>
#include <stdint.h>

#define Bx   8
#define Sx   2048
#define Hx   8
#define Mh   64
#define HMx  512

#define LOG2E 1.4426950408889634f
#define ONES2 0x3C003C00u

// ---------------------------------------------------------------------------
// Global scratch (allocation-free rule)
// ---------------------------------------------------------------------------
__device__ float g_xp[(size_t)Bx * Sx * HMx / 2];   // x  fp16 A-pack
__device__ float g_q [(size_t)Bx * Sx * HMx / 2];   // Q  fp16 A-pack (pre-scaled)
__device__ float g_k [(size_t)Bx * Sx * HMx / 2];   // K  fp16 B-pack
__device__ float g_v [(size_t)Bx * Sx * HMx / 2];   // V  fp16 B-pack
__device__ float g_m [(size_t)Bx * Sx * HMx / 2];   // msgs fp16 A-pack
__device__ float g_wq[512 * 256];                    // fp16 W-packs
__device__ float g_wk[512 * 256];
__device__ float g_wv[512 * 256];
__device__ float g_wo[512 * 256];
__device__ unsigned long long g_mb[(size_t)Bx * Sx * 32];  // mask bitwords

__device__ __forceinline__ uint32_t h2(float lo, float hi) {
    uint32_t r;
    asm("cvt.rn.f16x2.f32 %0, %1, %2;" : "=r"(r) : "f"(hi), "f"(lo));
    return r;
}
__device__ __forceinline__ uint32_t ex2h2(uint32_t x) {
    uint32_t r;
    asm("ex2.approx.f16x2 %0, %1;" : "=r"(r) : "r"(x));
    return r;
}
__device__ __forceinline__ void mma_f16(float* c, const uint32_t* a,
                                        uint32_t b0, uint32_t b1) {
    asm volatile(
        "mma.sync.aligned.m16n8k16.row.col.f32.f16.f16.f32 "
        "{%0,%1,%2,%3}, {%4,%5,%6,%7}, {%8,%9}, {%0,%1,%2,%3};"
        : "+f"(c[0]), "+f"(c[1]), "+f"(c[2]), "+f"(c[3])
        : "r"(a[0]), "r"(a[1]), "r"(a[2]), "r"(a[3]), "r"(b0), "r"(b1));
}
__device__ __forceinline__ void cp16(uint32_t smem_addr, const void* gptr) {
    asm volatile("cp.async.cg.shared.global [%0], [%1], 16;"
                 :: "r"(smem_addr), "l"(gptr));
}
#define CP_COMMIT()  asm volatile("cp.async.commit_group;" ::: "memory")
#define CP_WAIT1()   asm volatile("cp.async.wait_group 1;"  ::: "memory")
#define CP_WAIT0()   asm volatile("cp.async.wait_group 0;"  ::: "memory")

// ---------------------------------------------------------------------------
// Fused prep: blocks [0,8192) x->A-pack, [8192,9216) W->B-pack, rest mask bits
// ---------------------------------------------------------------------------
__global__ void prep_all_kernel(
    const float* __restrict__ x, const float* __restrict__ mask,
    const float* __restrict__ Wq, const float* __restrict__ Wk,
    const float* __restrict__ Wv, const float* __restrict__ Wo,
    __half* __restrict__ xp,
    __half* __restrict__ wq, __half* __restrict__ wk,
    __half* __restrict__ wv, __half* __restrict__ wo,
    unsigned long long* __restrict__ mb)
{
    int bid = blockIdx.x;
    if (bid < 8192) {
        int t  = bid * 256 + threadIdx.x;
        int r  = t >> 7;
        int c4 = (t & 127) << 2;
        float4 v = *(const float4*)&x[(size_t)r * 512 + c4];
        int mbr = r >> 4, qr = r & 7, hi = (r >> 3) & 1;
        float vv[4] = {v.x, v.y, v.z, v.w};
#pragma unroll
        for (int i = 0; i < 4; i++) {
            int c  = c4 + i;
            int dk = c >> 4, kk = c & 15;
            int reg  = hi + ((kk >> 3) << 1);
            int lane = qr * 4 + ((kk & 7) >> 1);
            size_t off = ((size_t)(mbr * 32 + dk) * 32 + lane) * 4 + reg;
            xp[off * 2 + (kk & 1)] = __float2half_rn(vv[i]);
        }
    } else if (bid < 9216) {
        int wi = (bid - 8192) >> 8;
        const float* Wsrc = (wi == 0) ? Wq : (wi == 1) ? Wk : (wi == 2) ? Wv : Wo;
        __half* wp        = (wi == 0) ? wq : (wi == 1) ? wk : (wi == 2) ? wv : wo;
        float scale       = (wi == 0) ? 0.125f : 1.0f;   // fold rsqrt(64) into Wq
        int t  = ((bid - 8192) & 255) * 256 + threadIdx.x;
        int k  = t >> 7;
        int c4 = (t & 127) << 2;
        float4 v = *(const float4*)&Wsrc[(size_t)k * 512 + c4];
        int dk = k >> 4, kk = k & 15;
        int s    = kk >> 3;
        int qcw  = (kk & 7) >> 1;
        int hsel = kk & 1;
        float vv[4] = {v.x, v.y, v.z, v.w};
#pragma unroll
        for (int i = 0; i < 4; i++) {
            int n  = c4 + i;
            int jg = n >> 3;
            int lane = (n & 7) * 4 + qcw;
            size_t off = ((size_t)(dk * 32 + (jg >> 1)) * 32 + lane) * 4
                       + (jg & 1) * 2 + s;
            wp[off * 2 + hsel] = __float2half_rn(vv[i] * scale);
        }
    } else {
        int warp = (bid - 9216) * 8 + (threadIdx.x >> 5);
        int lane = threadIdx.x & 31;
        const float* row = mask + (size_t)warp * 2048;
        unsigned long long* dst = mb + (size_t)warp * 32;
#pragma unroll 4
        for (int w = 0; w < 32; w++) {
            float m0 = row[w * 64 + lane];
            float m1 = row[w * 64 + 32 + lane];
            unsigned b0 = __ballot_sync(0xffffffffu, m0 > 0.5f);
            unsigned b1 = __ballot_sync(0xffffffffu, m1 > 0.5f);
            if (lane == 0)
                dst[w] = ((unsigned long long)b1 << 32) | b0;
        }
    }
}

// ---------------------------------------------------------------------------
// fp16 GEMM, M=32/warp, W staged in smem via cp.async double buffer.
// grid (8, 128), 128 thr. MODE: 0=fp32 out, 1=K pack, 2=V pack, 3=Q pack
// ---------------------------------------------------------------------------
template<int MODE>
__global__ void __launch_bounds__(128) gemm_f16_kernel(
    const uint32_t* __restrict__ Ap, const uint32_t* __restrict__ Wp,
    const float* __restrict__ bias, float* __restrict__ out, float bscale)
{
    __shared__ uint32_t Ws[2][2048];   // 2 x 8KB (4 dk-steps each)

    const int tid  = threadIdx.x;
    const int w    = tid >> 5;
    const int lane = tid & 31;
    const int qr   = lane >> 2;
    const int qc   = lane & 3;
    const int nb   = blockIdx.x;
    const int mb0  = blockIdx.y * 8 + w * 2;

    const uint32_t* wsrc = Wp + (size_t)nb * 512;   // + dk*4096 + i
    uint32_t ws_addr0 = (uint32_t)__cvta_generic_to_shared(&Ws[0][0]);

    // issue chunk 0 copy (dk 0..3)
#pragma unroll
    for (int d2 = 0; d2 < 4; d2++)
        cp16(ws_addr0 + (d2 * 512 + tid * 4) * 4,
             wsrc + (size_t)d2 * 4096 + tid * 4);
    CP_COMMIT();

    float o[2][8][4];
#pragma unroll
    for (int rt = 0; rt < 2; rt++)
#pragma unroll
        for (int j = 0; j < 8; j++)
#pragma unroll
            for (int u = 0; u < 4; u++) o[rt][j][u] = 0.f;

    const uint4* ab = (const uint4*)(Ap + (size_t)mb0 * 4096 + lane * 4);

    for (int cc = 0; cc < 8; cc++) {
        const int buf = cc & 1;
        if (cc + 1 < 8) {
            uint32_t wa = (uint32_t)__cvta_generic_to_shared(&Ws[buf ^ 1][0]);
            const uint32_t* src = wsrc + (size_t)(cc + 1) * 4 * 4096;
#pragma unroll
            for (int d2 = 0; d2 < 4; d2++)
                cp16(wa + (d2 * 512 + tid * 4) * 4,
                     src + (size_t)d2 * 4096 + tid * 4);
            CP_COMMIT();
            CP_WAIT1();
        } else {
            CP_WAIT0();
        }
        __syncthreads();

#pragma unroll
        for (int d2 = 0; d2 < 4; d2++) {
            int dk = cc * 4 + d2;
            uint4 a0 = ab[dk * 32];
            uint4 a1 = ab[dk * 32 + 1024];
            uint32_t qa0[4] = {a0.x, a0.y, a0.z, a0.w};
            uint32_t qa1[4] = {a1.x, a1.y, a1.z, a1.w};
#pragma unroll
            for (int jp = 0; jp < 4; jp++) {
                uint4 wv = *(const uint4*)&Ws[buf][d2 * 512 + jp * 128 + lane * 4];
                mma_f16(o[0][jp * 2],     qa0, wv.x, wv.y);
                mma_f16(o[0][jp * 2 + 1], qa0, wv.z, wv.w);
                mma_f16(o[1][jp * 2],     qa1, wv.x, wv.y);
                mma_f16(o[1][jp * 2 + 1], qa1, wv.z, wv.w);
            }
        }
        __syncthreads();
    }

    const int n0 = nb * 64;

#pragma unroll
    for (int rt = 0; rt < 2; rt++) {
        const int mb  = mb0 + rt;
        const int rlo = mb * 16 + qr;

        if (MODE == 0) {
            const int rhi = rlo + 8;
#pragma unroll
            for (int jc = 0; jc < 8; jc++) {
                int col = n0 + jc * 8 + 2 * qc;
                float2 bb = *(const float2*)&bias[col];
                float2 lo_v = {o[rt][jc][0] + bb.x, o[rt][jc][1] + bb.y};
                float2 hi_v = {o[rt][jc][2] + bb.x, o[rt][jc][3] + bb.y};
                *(float2*)&out[(size_t)rlo * 512 + col] = lo_v;
                *(float2*)&out[(size_t)rhi * 512 + col] = hi_v;
            }
        } else if (MODE == 3) {
            uint32_t* ob = (uint32_t*)out + ((size_t)(mb * 32 + nb * 4) * 32 + lane) * 4;
#pragma unroll
            for (int jc = 0; jc < 8; jc++) {
                float2 bb = *(const float2*)&bias[n0 + jc * 8 + 2 * qc];
                bb.x *= bscale; bb.y *= bscale;
                uint32_t* base = ob + (size_t)(jc >> 1) * 128 + (jc & 1) * 2;
                base[0] = h2(o[rt][jc][0] + bb.x, o[rt][jc][1] + bb.y);
                base[1] = h2(o[rt][jc][2] + bb.x, o[rt][jc][3] + bb.y);
            }
        } else if (MODE == 1) {
            int b   = rlo >> 11;
            int tok = rlo & 2047;
            int jp  = tok >> 4;
            uint32_t* ob = (uint32_t*)out +
                (((size_t)(b * 8 + nb) * 4) * 128 + jp) * 128 + lane * 4;
#pragma unroll
            for (int jc = 0; jc < 8; jc++) {
                float2 bb = *(const float2*)&bias[n0 + jc * 8 + 2 * qc];
                uint32_t* base = ob + (size_t)(jc >> 1) * 16384 + (jc & 1);
                base[0] = h2(o[rt][jc][0] + bb.x, o[rt][jc][1] + bb.y);
                base[2] = h2(o[rt][jc][2] + bb.x, o[rt][jc][3] + bb.y);
            }
        } else {
            int b   = rlo >> 11;
            int tok = rlo & 2047;
            int kc  = tok >> 4;
            int hsel = qr & 1;
            __half* ob = (__half*)((uint32_t*)out +
                (((size_t)(b * 8 + nb) * 128 + kc) * 4) * 128);
#pragma unroll
            for (int jc = 0; jc < 8; jc++) {
                float2 bb = *(const float2*)&bias[n0 + jc * 8 + 2 * qc];
                size_t jbase = (size_t)(jc >> 1) * 128;
#pragma unroll
                for (int e = 0; e < 2; e++) {
                    int lane_v = (2 * qc + e) * 4 + (qr >> 1);
                    size_t u32i = jbase + lane_v * 4 + (jc & 1) * 2;
                    float bv = e ? bb.y : bb.x;
                    ob[(u32i + 0) * 2 + hsel] = __float2half_rn(o[rt][jc][e]     + bv);
                    ob[(u32i + 1) * 2 + hsel] = __float2half_rn(o[rt][jc][e + 2] + bv);
                }
            }
        }
    }
}

// ---------------------------------------------------------------------------
// fp16 flash attention: K/V staged in smem via cp.async double buffer.
// Block = (64 queries, b, h); 4 warps x 16 rows; key chunks of 64.
// ---------------------------------------------------------------------------
__global__ void __launch_bounds__(128) attn_tc_kernel(
    const float* __restrict__ Qp, const float* __restrict__ Kp,
    const float* __restrict__ Vp, const unsigned long long* __restrict__ mb,
    float* __restrict__ Mp)
{
    __shared__ uint32_t Ks[2][2048];   // 2 x 8KB
    __shared__ uint32_t Vs[2][2048];   // 2 x 8KB

    const int h  = blockIdx.z;
    const int b  = blockIdx.y;
    const int q0 = blockIdx.x * 64;
    const int tid  = threadIdx.x;
    const int w    = tid >> 5;
    const int lane = tid & 31;
    const int qr   = lane >> 2;
    const int qc   = lane & 3;

    const int mbq = b * 128 + (q0 >> 4) + w;

    const size_t bh = (size_t)(b * 8 + h);
    const uint32_t* kglob = (const uint32_t*)Kp + bh * 65536;   // 4*16384
    const uint32_t* vglob = (const uint32_t*)Vp + bh * 65536;   // 128*512

    // issue chunk 0 K/V copies
    {
        uint32_t ka = (uint32_t)__cvta_generic_to_shared(&Ks[0][0]);
        uint32_t va = (uint32_t)__cvta_generic_to_shared(&Vs[0][0]);
#pragma unroll
        for (int d = 0; d < 4; d++)
            cp16(ka + (d * 512 + tid * 4) * 4,
                 kglob + (size_t)(d * 128) * 128 + tid * 4);
#pragma unroll
        for (int r = 0; r < 4; r++)
            cp16(va + (r * 512 + tid * 4) * 4,
                 vglob + (size_t)r * 512 + tid * 4);
        CP_COMMIT();
    }

    // ---- Q fragments: 4 x LDG.128 (fp16 A-pack, pre-scaled), persistent ----
    uint32_t qa[4][4];
    {
        const uint4* qb = (const uint4*)((const uint32_t*)Qp +
            ((size_t)(mbq * 32 + h * 4) * 32 + lane) * 4);
#pragma unroll
        for (int d = 0; d < 4; d++) {
            uint4 a4 = qb[d * 32];
            qa[d][0] = a4.x; qa[d][1] = a4.y; qa[d][2] = a4.z; qa[d][3] = a4.w;
        }
    }

    float o[8][4];
#pragma unroll
    for (int j = 0; j < 8; j++)
#pragma unroll
        for (int u = 0; u < 4; u++) o[j][u] = 0.f;
    float osum[4] = {0.f, 0.f, 0.f, 0.f};
    float m_lo = -INFINITY, m_hi = -INFINITY;

    const int rlo = w * 16 + qr;
    const int rhi = rlo + 8;
    const unsigned long long* mb_lo = mb + (size_t)(b * Sx + q0 + rlo) * 32;
    const unsigned long long* mb_hi = mb + (size_t)(b * Sx + q0 + rhi) * 32;

    const int bidx0 = 2 * qc;

    for (int cc = 0; cc < 32; cc++) {
        const int buf = cc & 1;
        if (cc + 1 < 32) {
            const int jn = (cc + 1) * 4;
            uint32_t ka = (uint32_t)__cvta_generic_to_shared(&Ks[buf ^ 1][0]);
            uint32_t va = (uint32_t)__cvta_generic_to_shared(&Vs[buf ^ 1][0]);
#pragma unroll
            for (int d = 0; d < 4; d++)
                cp16(ka + (d * 512 + tid * 4) * 4,
                     kglob + (size_t)(d * 128 + jn) * 128 + tid * 4);
#pragma unroll
            for (int r = 0; r < 4; r++)
                cp16(va + (r * 512 + tid * 4) * 4,
                     vglob + (size_t)(jn + r) * 512 + tid * 4);
            CP_COMMIT();
            CP_WAIT1();
        } else {
            CP_WAIT0();
        }
        __syncthreads();

        // ---- S = Q K^T (from smem) ----
        float s[8][4];
#pragma unroll
        for (int j = 0; j < 8; j++)
#pragma unroll
            for (int u = 0; u < 4; u++) s[j][u] = 0.f;
#pragma unroll
        for (int d = 0; d < 4; d++) {
#pragma unroll
            for (int jp = 0; jp < 4; jp++) {
                uint4 kv = *(const uint4*)&Ks[buf][d * 512 + jp * 128 + lane * 4];
                mma_f16(s[jp * 2],     qa[d], kv.x, kv.y);
                mma_f16(s[jp * 2 + 1], qa[d], kv.z, kv.w);
            }
        }

        // ---- mask (bitwords) + row max ----
        unsigned long long wlo = mb_lo[cc >> 1];
        unsigned long long whi = mb_hi[cc >> 1];
        int sh = (cc & 1) ? 0 : 0;   // (placeholder, chunk=64 -> word index cc/1)
        // NOTE: chunk covers 64 keys = exactly one 64-bit word:
        wlo = mb_lo[cc];
        whi = mb_hi[cc];
        (void)sh;
        float rmax_lo = -INFINITY, rmax_hi = -INFINITY;
#pragma unroll
        for (int j = 0; j < 8; j++) {
            int idx = j * 8 + bidx0;
            s[j][0] = ((wlo >> idx) & 1ull)       ? s[j][0] : -INFINITY;
            s[j][1] = ((wlo >> (idx + 1)) & 1ull) ? s[j][1] : -INFINITY;
            s[j][2] = ((whi >> idx) & 1ull)       ? s[j][2] : -INFINITY;
            s[j][3] = ((whi >> (idx + 1)) & 1ull) ? s[j][3] : -INFINITY;
            rmax_lo = fmaxf(rmax_lo, fmaxf(s[j][0], s[j][1]));
            rmax_hi = fmaxf(rmax_hi, fmaxf(s[j][2], s[j][3]));
        }
        rmax_lo = fmaxf(rmax_lo, __shfl_xor_sync(0xffffffff, rmax_lo, 1));
        rmax_lo = fmaxf(rmax_lo, __shfl_xor_sync(0xffffffff, rmax_lo, 2));
        rmax_hi = fmaxf(rmax_hi, __shfl_xor_sync(0xffffffff, rmax_hi, 1));
        rmax_hi = fmaxf(rmax_hi, __shfl_xor_sync(0xffffffff, rmax_hi, 2));

        float mn_lo = fmaxf(m_lo, rmax_lo);
        float mn_hi = fmaxf(m_hi, rmax_hi);
        float safe_lo = (mn_lo > -INFINITY) ? mn_lo : 0.f;
        float safe_hi = (mn_hi > -INFINITY) ? mn_hi : 0.f;
        float al = __expf(m_lo - safe_lo);
        float ah = __expf(m_hi - safe_hi);
        m_lo = mn_lo;
        m_hi = mn_hi;

        // ---- P = exp2((s - m)*log2e) in f16x2 ----
        float clo = safe_lo * LOG2E;
        float chi = safe_hi * LOG2E;
        uint32_t p[8][2];
#pragma unroll
        for (int j = 0; j < 8; j++) {
            float t0f = fmaf(s[j][0], LOG2E, -clo);
            float t1f = fmaf(s[j][1], LOG2E, -clo);
            float t2f = fmaf(s[j][2], LOG2E, -chi);
            float t3f = fmaf(s[j][3], LOG2E, -chi);
            p[j][0] = ex2h2(h2(t0f, t1f));
            p[j][1] = ex2h2(h2(t2f, t3f));
        }

        // ---- rescale accumulators ----
#pragma unroll
        for (int j = 0; j < 8; j++) {
            o[j][0] *= al; o[j][1] *= al;
            o[j][2] *= ah; o[j][3] *= ah;
        }
        osum[0] *= al; osum[1] *= al;
        osum[2] *= ah; osum[3] *= ah;

        // ---- O += P V ; row sums via ones-MMA (V from smem) ----
#pragma unroll
        for (int kc = 0; kc < 4; kc++) {
            uint32_t a[4];
            a[0] = p[2 * kc][0];
            a[1] = p[2 * kc][1];
            a[2] = p[2 * kc + 1][0];
            a[3] = p[2 * kc + 1][1];
#pragma unroll
            for (int jp = 0; jp < 4; jp++) {
                uint4 vv = *(const uint4*)&Vs[buf][kc * 512 + jp * 128 + lane * 4];
                mma_f16(o[jp * 2],     a, vv.x, vv.y);
                mma_f16(o[jp * 2 + 1], a, vv.z, vv.w);
            }
            mma_f16(osum, a, ONES2, ONES2);
        }
        __syncthreads();
    }

    // ---- epilogue: normalize, write msgs in fp16 A-pack ----
    float il_lo = (osum[0] > 0.f) ? (1.0f / osum[0]) : 0.f;
    float il_hi = (osum[2] > 0.f) ? (1.0f / osum[2]) : 0.f;
    uint32_t* ob = (uint32_t*)Mp + ((size_t)(mbq * 32 + h * 4) * 32 + lane) * 4;
#pragma unroll
    for (int jc = 0; jc < 8; jc++) {
        uint32_t* base = ob + (size_t)(jc >> 1) * 128 + (jc & 1) * 2;
        base[0] = h2(o[jc][0] * il_lo, o[jc][1] * il_lo);
        base[1] = h2(o[jc][2] * il_hi, o[jc][3] * il_hi);
    }
}

// ---------------------------------------------------------------------------
extern "C" void kernel_launch(void* const* d_in, const int* in_sizes, int n_in,
                              void* d_out, int out_size)
{
    (void)in_sizes; (void)n_in; (void)out_size;
    const float* x    = (const float*)d_in[0];
    const float* mask = (const float*)d_in[1];
    const float* Wq   = (const float*)d_in[2];
    const float* Wk   = (const float*)d_in[3];
    const float* Wv   = (const float*)d_in[4];
    const float* bq   = (const float*)d_in[5];
    const float* bk   = (const float*)d_in[6];
    const float* bv   = (const float*)d_in[7];
    const float* Wo   = (const float*)d_in[8];
    const float* bo   = (const float*)d_in[9];
    float* out = (float*)d_out;

    float *xp, *qp, *kp, *vp, *mp, *wqp, *wkp, *wvp, *wop;
    unsigned long long* mbp;
    cudaGetSymbolAddress((void**)&xp,  g_xp);
    cudaGetSymbolAddress((void**)&qp,  g_q);
    cudaGetSymbolAddress((void**)&kp,  g_k);
    cudaGetSymbolAddress((void**)&vp,  g_v);
    cudaGetSymbolAddress((void**)&mp,  g_m);
    cudaGetSymbolAddress((void**)&wqp, g_wq);
    cudaGetSymbolAddress((void**)&wkp, g_wk);
    cudaGetSymbolAddress((void**)&wvp, g_wv);
    cudaGetSymbolAddress((void**)&wop, g_wo);
    cudaGetSymbolAddress((void**)&mbp, g_mb);

    prep_all_kernel<<<11264, 256>>>(x, mask, Wq, Wk, Wv, Wo,
                                    (__half*)xp, (__half*)wqp, (__half*)wkp,
                                    (__half*)wvp, (__half*)wop, mbp);

    dim3 gg(8, 128);
    gemm_f16_kernel<3><<<gg, 128>>>((const uint32_t*)xp, (const uint32_t*)wqp, bq, qp, 0.125f);
    gemm_f16_kernel<1><<<gg, 128>>>((const uint32_t*)xp, (const uint32_t*)wkp, bk, kp, 1.0f);
    gemm_f16_kernel<2><<<gg, 128>>>((const uint32_t*)xp, (const uint32_t*)wvp, bv, vp, 1.0f);

    dim3 ga(Sx / 64, Bx, Hx);   // (32, 8, 8)
    attn_tc_kernel<<<ga, 128>>>(qp, kp, vp, mbp, mp);

    gemm_f16_kernel<0><<<gg, 128>>>((const uint32_t*)mp, (const uint32_t*)wop, bo, out, 1.0f);
}